// round 11
// baseline (speedup 1.0000x reference)
#include <cuda_runtime.h>
#include <stdint.h>
#include <math.h>

#define H 128
#define W 128
#define HW (H*W)
#define NF 64
#define TT 5
#define BB 2

// ---------------- scratch ----------------
__device__ float g_feats[BB*TT*NF*HW];       // NCHW
__device__ float g_fnhwc[BB*TT*HW*NF];       // NHWC
__device__ float g_half[BB*6*27*HW];
__device__ float g_wt[9*64*64];              // dcn weights [k][c][o]
__device__ float g_hw[2*64*9*32];            // half-conv weights [icg][c][tap][slot]

// ---------------- f32x2 helpers ----------------
typedef unsigned long long ull;
__device__ __forceinline__ ull pk2(float lo, float hi) {
    ull r; asm("mov.b64 %0, {%1,%2};" : "=l"(r) : "f"(lo), "f"(hi)); return r;
}
__device__ __forceinline__ void ffma2(ull& d, ull a, ull b) {
    asm("fma.rn.f32x2 %0, %1, %2, %0;" : "+l"(d) : "l"(a), "l"(b));
}
__device__ __forceinline__ float2 upk2(ull v) {
    float2 f; asm("mov.b64 {%0,%1}, %2;" : "=f"(f.x), "=f"(f.y) : "l"(v)); return f;
}
__device__ __forceinline__ void cp_async4(uint32_t saddr, const float* g, bool pred) {
    int bytes = pred ? 4 : 0;
    asm volatile("cp.async.ca.shared.global [%0], [%1], 4, %2;" :: "r"(saddr), "l"(g), "r"(bytes));
}
__device__ __forceinline__ void cp_async16(uint32_t saddr, const float* g, bool pred) {
    int bytes = pred ? 16 : 0;
    asm volatile("cp.async.ca.shared.global [%0], [%1], 16, %2;" :: "r"(saddr), "l"(g), "r"(bytes));
}

// ---------------- W-prep: dcn weights ----------------
__global__ void wprep_kernel(const float* __restrict__ dcn_w) {
    int i = blockIdx.x * blockDim.x + threadIdx.x;
    if (i >= 9*64*64) return;
    int o = i & 63;
    int c = (i >> 6) & 63;
    int k = i >> 12;
    g_wt[i] = dcn_w[(o*64 + c)*9 + k];
}

// ---------------- W-prep: half-conv weights ----------------
__global__ void whprep_kernel(const float* __restrict__ offm_w) {
    int i = blockIdx.x * blockDim.x + threadIdx.x;
    if (i >= 2*64*9*32) return;
    int slot = i & 31;
    int rest = i >> 5;
    int tap = rest % 9;
    int cc  = rest / 9;
    int qq = slot >> 3, ii = slot & 7;
    int oc = qq*7 + ii;
    float v = 0.f;
    if (ii < 7 && oc < 27) v = offm_w[(oc*128 + cc)*9 + tap];
    g_hw[i] = v;
}

// ---------------- kernel A: 3->64 conv3x3 + bias + PReLU -> NCHW ----------------
__global__ void __launch_bounds__(256) init_conv_kernel(
    const float* __restrict__ x, const float* __restrict__ wgt,
    const float* __restrict__ bias, const float* __restrict__ prelu_a)
{
    __shared__ float sx[3][18][18];
    __shared__ __align__(8) float sw[27*64];
    __shared__ __align__(8) float sb[64];
    int tid = threadIdx.x;
    int n = blockIdx.y;
    int ty0 = (blockIdx.x >> 3) * 16;
    int tx0 = (blockIdx.x & 7) * 16;

    for (int idx = tid; idx < 1728; idx += 256) {
        int oc = idx & 63;
        int r = idx >> 6;
        int ic = r / 9, tap = r % 9;
        sw[idx] = wgt[(oc*3 + ic)*9 + tap];
    }
    if (tid < 64) sb[tid] = bias[tid];

    const float* xin = x + n*3*HW;
    for (int idx = tid; idx < 3*18*18; idx += 256) {
        int c = idx / 324;
        int r = (idx / 18) % 18;
        int col = idx % 18;
        int gy = ty0 + r - 1, gx = tx0 + col - 1;
        float v = 0.f;
        if (gy >= 0 && gy < H && gx >= 0 && gx < W) v = xin[c*HW + gy*W + gx];
        sx[c][r][col] = v;
    }
    __syncthreads();

    int ly = tid >> 4, lx = tid & 15;
    ull acc2[32];
    #pragma unroll
    for (int o2 = 0; o2 < 32; o2++) acc2[o2] = *(const ull*)&sb[2*o2];

    for (int ic = 0; ic < 3; ic++) {
        #pragma unroll
        for (int tap = 0; tap < 9; tap++) {
            int dy = tap / 3, dx = tap % 3;
            float v = sx[ic][ly + dy][lx + dx];
            ull v2 = pk2(v, v);
            const ull* wp = (const ull*)&sw[(ic*9 + tap)*64];
            #pragma unroll
            for (int o2 = 0; o2 < 32; o2++) ffma2(acc2[o2], v2, wp[o2]);
        }
    }
    float a = prelu_a[0];
    int pix = (ty0 + ly)*W + (tx0 + lx);
    float* dst = g_feats + (size_t)n*NF*HW + pix;
    #pragma unroll
    for (int o2 = 0; o2 < 32; o2++) {
        float2 f = upk2(acc2[o2]);
        dst[(2*o2)*HW]   = (f.x > 0.f) ? f.x : a*f.x;
        dst[(2*o2+1)*HW] = (f.y > 0.f) ? f.y : a*f.y;
    }
}

// ---------------- transpose NCHW -> NHWC ----------------
__global__ void __launch_bounds__(256) transpose_kernel()
{
    __shared__ float tile[64][65];
    int tid = threadIdx.x;
    int n = blockIdx.y;
    int px0 = blockIdx.x * 64;
    const float* src = g_feats + (size_t)n*NF*HW + px0;
    float* dst = g_fnhwc + ((size_t)n*HW + px0)*64;

    #pragma unroll
    for (int i = 0; i < 16; i++) {
        int idx = tid + i*256;
        int c = idx >> 6, xx = idx & 63;
        tile[c][xx] = src[c*HW + xx];
    }
    __syncthreads();
    #pragma unroll
    for (int i = 0; i < 16; i++) {
        int idx = tid + i*256;
        int p = idx >> 6, c = idx & 63;
        dst[p*64 + c] = tile[c][p];
    }
}

// ---------------- kernel B v6: half offset-conv (unchanged from R10) ----------------
__global__ void __launch_bounds__(128, 4) half_conv_kernel()
{
    __shared__ __align__(16) float st[2][8][10][44];
    __shared__ __align__(16) float ws[2][2304];
    int tid = threadIdx.x;
    int task = blockIdx.y;
    int b = task / 6, s = task % 6;
    int tsel = (s == 0) ? 0 : (s - 1);
    int icg  = (s == 0) ? 0 : 1;
    int y0 = (blockIdx.x >> 2) * 8;
    int x0 = (blockIdx.x & 3) * 32;

    const float* src  = g_feats + (size_t)((b*TT + tsel)*NF)*HW;
    const float* wsrc = g_hw + icg*64*9*32;

    int q    = tid >> 5;
    int lane = tid & 31;
    int ly   = lane >> 2;
    int lx   = lane & 3;

    uint32_t st_sm = (uint32_t)__cvta_generic_to_shared(&st[0][0][0][0]);
    uint32_t ws_sm = (uint32_t)__cvta_generic_to_shared(&ws[0][0]);
    const uint32_t ST_BUF = 8*10*44*4;
    const uint32_t WS_BUF = 2304*4;

    auto stage = [&](int icb, int buf) {
        uint32_t stb = st_sm + buf*ST_BUF;
        for (int idx = tid; idx < 640; idx += 128) {
            int c = idx / 80;
            int rem = idx % 80;
            int rr = rem >> 3, seg = rem & 7;
            int gy = y0 + rr - 1;
            bool p = (gy >= 0) && (gy < H);
            const float* g = src + (icb + c)*HW + (p ? gy : 0)*W + x0 + seg*4;
            cp_async16(stb + (((c*10 + rr)*44) + 4 + seg*4)*4, g, p);
        }
        for (int idx = tid; idx < 160; idx += 128) {
            int c = idx / 20;
            int rem = idx % 20;
            int rr = rem >> 1, side = rem & 1;
            int gy = y0 + rr - 1;
            int gx = side ? (x0 + 32) : (x0 - 1);
            bool p = (gy >= 0) && (gy < H) && (gx >= 0) && (gx < W);
            int col = side ? 36 : 3;
            cp_async4(stb + (((c*10 + rr)*44) + col)*4, src + (icb + c)*HW + (p ? gy*W + gx : 0), p);
        }
        uint32_t wsb = ws_sm + buf*WS_BUF;
        const float* base = wsrc + icb*9*32;
        for (int idx = tid; idx < 576; idx += 128) {
            cp_async16(wsb + idx*16, base + idx*4, true);
        }
    };

    ull acc2[4][8];
    #pragma unroll
    for (int o2 = 0; o2 < 4; o2++)
        #pragma unroll
        for (int p = 0; p < 8; p++) acc2[o2][p] = 0ULL;

    stage(0, 0);
    asm volatile("cp.async.commit_group;");

    for (int ci = 0; ci < 8; ci++) {
        int buf = ci & 1;
        if (ci < 7) {
            stage((ci + 1)*8, buf ^ 1);
            asm volatile("cp.async.commit_group;");
            asm volatile("cp.async.wait_group 1;");
        } else {
            asm volatile("cp.async.wait_group 0;");
        }
        __syncthreads();

        const float (*stb)[10][44] = st[buf];
        const float* wsb = ws[buf];
        int cb = 4 + 8*lx;

        #pragma unroll
        for (int c = 0; c < 8; c++) {
            #pragma unroll
            for (int dy = 0; dy < 3; dy++) {
                const float* rp = &stb[c][ly + dy][0];
                float4 a  = *(const float4*)(rp + cb);
                float4 bb = *(const float4*)(rp + cb + 4);
                float hl = rp[cb - 1], hr = rp[cb + 8];
                ull iv[10];
                iv[0] = pk2(hl, hl);
                iv[1] = pk2(a.x, a.x);  iv[2] = pk2(a.y, a.y);
                iv[3] = pk2(a.z, a.z);  iv[4] = pk2(a.w, a.w);
                iv[5] = pk2(bb.x, bb.x); iv[6] = pk2(bb.y, bb.y);
                iv[7] = pk2(bb.z, bb.z); iv[8] = pk2(bb.w, bb.w);
                iv[9] = pk2(hr, hr);
                #pragma unroll
                for (int dx = 0; dx < 3; dx++) {
                    const ulonglong2* wp = (const ulonglong2*)&wsb[(c*9 + dy*3 + dx)*32 + q*8];
                    ulonglong2 wA = wp[0];
                    ulonglong2 wB = wp[1];
                    #pragma unroll
                    for (int p = 0; p < 8; p++) {
                        ull v = iv[p + dx];
                        ffma2(acc2[0][p], v, wA.x);
                        ffma2(acc2[1][p], v, wA.y);
                        ffma2(acc2[2][p], v, wB.x);
                        ffma2(acc2[3][p], v, wB.y);
                    }
                }
            }
        }
        __syncthreads();
    }

    float* dst = g_half + (size_t)(task*27)*HW + (y0 + ly)*W + x0 + 8*lx;
    #pragma unroll
    for (int i = 0; i < 7; i++) {
        int oc = q*7 + i;
        if (oc >= 27) break;
        float4 lo, hi;
        float* lv = (float*)&lo;
        float* hv = (float*)&hi;
        #pragma unroll
        for (int p = 0; p < 4; p++) {
            float2 f = upk2(acc2[i >> 1][p]);
            lv[p] = (i & 1) ? f.y : f.x;
        }
        #pragma unroll
        for (int p = 4; p < 8; p++) {
            float2 f = upk2(acc2[i >> 1][p]);
            hv[p - 4] = (i & 1) ? f.y : f.x;
        }
        *(float4*)(dst + (size_t)oc*HW) = lo;
        *(float4*)(dst + (size_t)oc*HW + 4) = hi;
    }
}

// ---------------- kernel C v3: dcn pipelined, 64oc x 64px, double-buffered S ----------------
// 128 threads; GEMM role: ty=tid>>4 (8 oc), tx=tid&15 (4 px); gather role: qq=tid&7 (ch pair), pxw=tid>>3
// S[c][px] with physical 4-px group = logical ^ (c & 15)
__global__ void __launch_bounds__(128, 4) dcn_kernel(
    const float* __restrict__ offm_b, const float* __restrict__ dcn_b,
    float* __restrict__ out)
{
    __shared__ __align__(16) float S[2][64*64];
    __shared__ int   mAi[2][4][64];
    __shared__ float mWm[2][4][64];

    int tid = threadIdx.x;
    int jb = blockIdx.y;
    int j = jb >> 1, b = jb & 1;
    int y  = blockIdx.x >> 1;
    int x0 = (blockIdx.x & 1) * 64;

    const float* fb = g_fnhwc + (size_t)(b*TT + j)*HW*64;
    const float* h0 = g_half + (size_t)((b*6 + 0)*27)*HW;
    const float* h1 = g_half + (size_t)((b*6 + 1 + j)*27)*HW;

    int tx = tid & 15, ty = tid >> 4;
    int qq = tid & 7, pxw = tid >> 3;

    // ---- meta computation for tap t into buffer mb (threads 0..63, px = tid) ----
    auto meta = [&](int k, int mb) {
        if (tid < 64) {
            int gx = x0 + tid;
            int pix = y*W + gx;
            float oy = h0[k*HW + pix] + h1[k*HW + pix] + offm_b[k];
            float ox = h0[(9+k)*HW + pix] + h1[(9+k)*HW + pix] + offm_b[9+k];
            float mm = h0[(18+k)*HW + pix] + h1[(18+k)*HW + pix] + offm_b[18+k];
            float mask = 1.f / (1.f + expf(-mm));
            float py  = (float)(y + (k/3) - 1) + oy;
            float pxf = (float)(gx + (k%3) - 1) + ox;
            float y0f = floorf(py), x0f = floorf(pxf);
            float lyf = py - y0f, lxf = pxf - x0f;
            int yi = (int)y0f, xi = (int)x0f;
            bool vy0 = (yi >= 0) & (yi < H);
            bool vy1 = (yi >= -1) & (yi < H-1);
            bool vx0 = (xi >= 0) & (xi < W);
            bool vx1 = (xi >= -1) & (xi < W-1);
            int yc0 = min(max(yi, 0), H-1);
            int yc1 = min(max(yi+1, 0), H-1);
            int xc0 = min(max(xi, 0), W-1);
            int xc1 = min(max(xi+1, 0), W-1);
            float wy0 = 1.f - lyf, wy1 = lyf, wx0 = 1.f - lxf, wx1 = lxf;
            mAi[mb][0][tid] = (yc0*W + xc0) * 64;  mWm[mb][0][tid] = (vy0 && vx0) ? wy0*wx0*mask : 0.f;
            mAi[mb][1][tid] = (yc0*W + xc1) * 64;  mWm[mb][1][tid] = (vy0 && vx1) ? wy0*wx1*mask : 0.f;
            mAi[mb][2][tid] = (yc1*W + xc0) * 64;  mWm[mb][2][tid] = (vy1 && vx0) ? wy1*wx0*mask : 0.f;
            mAi[mb][3][tid] = (yc1*W + xc1) * 64;  mWm[mb][3][tid] = (vy1 && vx1) ? wy1*wx1*mask : 0.f;
        }
    };

    // ---- gather issue: load 8 float4 for pass p of tap meta-buffer mb ----
    auto issue = [&](int p, int mb, float4* va, float4* vb) {
        int px = p*16 + pxw;
        #pragma unroll
        for (int c = 0; c < 4; c++) {
            int a = mAi[mb][c][px];
            va[c] = __ldg((const float4*)(fb + a + qq*4));
            vb[c] = __ldg((const float4*)(fb + a + (qq + 8)*4));
        }
    };
    // ---- gather commit: weighted combine + store into S[sb] ----
    auto commit = [&](int p, int mb, int sb, const float4* va, const float4* vb) {
        int px = p*16 + pxw;
        int g = px >> 2, sub = px & 3;
        float w0 = mWm[mb][0][px], w1 = mWm[mb][1][px];
        float w2 = mWm[mb][2][px], w3 = mWm[mb][3][px];
        float4 r0, r1;
        r0.x = fmaf(w3, va[3].x, fmaf(w2, va[2].x, fmaf(w1, va[1].x, w0*va[0].x)));
        r0.y = fmaf(w3, va[3].y, fmaf(w2, va[2].y, fmaf(w1, va[1].y, w0*va[0].y)));
        r0.z = fmaf(w3, va[3].z, fmaf(w2, va[2].z, fmaf(w1, va[1].z, w0*va[0].z)));
        r0.w = fmaf(w3, va[3].w, fmaf(w2, va[2].w, fmaf(w1, va[1].w, w0*va[0].w)));
        r1.x = fmaf(w3, vb[3].x, fmaf(w2, vb[2].x, fmaf(w1, vb[1].x, w0*vb[0].x)));
        r1.y = fmaf(w3, vb[3].y, fmaf(w2, vb[2].y, fmaf(w1, vb[1].y, w0*vb[0].y)));
        r1.z = fmaf(w3, vb[3].z, fmaf(w2, vb[2].z, fmaf(w1, vb[1].z, w0*vb[0].z)));
        r1.w = fmaf(w3, vb[3].w, fmaf(w2, vb[2].w, fmaf(w1, vb[1].w, w0*vb[0].w)));
        const float* rr0 = (const float*)&r0;
        const float* rr1 = (const float*)&r1;
        #pragma unroll
        for (int i = 0; i < 4; i++) {
            int cA = qq*4 + i;
            S[sb][cA*64 + ((g ^ (cA & 15)) << 2) + sub] = rr0[i];
            int cB = (qq + 8)*4 + i;
            S[sb][cB*64 + ((g ^ (cB & 15)) << 2) + sub] = rr1[i];
        }
    };

    ull acc2[8][2];
    #pragma unroll
    for (int o = 0; o < 8; o++) { acc2[o][0] = 0ULL; acc2[o][1] = 0ULL; }

    // ---- prologue: meta(0) + gather tap 0 into S[0] ----
    meta(0, 0);
    __syncthreads();
    {
        float4 va[4], vb[4];
        #pragma unroll
        for (int p = 0; p < 4; p++) {
            issue(p, 0, va, vb);
            commit(p, 0, 0, va, vb);
        }
    }

    // ---- main loop over taps ----
    for (int k = 0; k < 9; k++) {
        int sb_r = k & 1;
        int sb_w = (k + 1) & 1;
        if (k < 8) meta(k + 1, sb_w);
        __syncthreads();    // gather(k) stores + meta(k+1) visible; GEMM(k) may start

        const float* wbase = g_wt + k*4096;
        #pragma unroll
        for (int c4 = 0; c4 < 4; c4++) {
            float4 va[4], vb[4];
            if (k < 8) issue(c4, sb_w, va, vb);
            #pragma unroll
            for (int u = 0; u < 16; u++) {
                int kk = c4*16 + u;
                float4 wA = __ldg((const float4*)(wbase + kk*64 + ty*8));
                float4 wB = __ldg((const float4*)(wbase + kk*64 + ty*8 + 4));
                const ull* bp = (const ull*)&S[sb_r][kk*64 + ((tx ^ (kk & 15)) << 2)];
                ull b0 = bp[0], b1 = bp[1];
                ull sv;
                sv = pk2(wA.x, wA.x); ffma2(acc2[0][0], sv, b0); ffma2(acc2[0][1], sv, b1);
                sv = pk2(wA.y, wA.y); ffma2(acc2[1][0], sv, b0); ffma2(acc2[1][1], sv, b1);
                sv = pk2(wA.z, wA.z); ffma2(acc2[2][0], sv, b0); ffma2(acc2[2][1], sv, b1);
                sv = pk2(wA.w, wA.w); ffma2(acc2[3][0], sv, b0); ffma2(acc2[3][1], sv, b1);
                sv = pk2(wB.x, wB.x); ffma2(acc2[4][0], sv, b0); ffma2(acc2[4][1], sv, b1);
                sv = pk2(wB.y, wB.y); ffma2(acc2[5][0], sv, b0); ffma2(acc2[5][1], sv, b1);
                sv = pk2(wB.z, wB.z); ffma2(acc2[6][0], sv, b0); ffma2(acc2[6][1], sv, b1);
                sv = pk2(wB.w, wB.w); ffma2(acc2[7][0], sv, b0); ffma2(acc2[7][1], sv, b1);
            }
            if (k < 8) commit(c4, sb_w, sb_w, va, vb);
        }
    }

    // ---- epilogue ----
    float* ob = out + (size_t)jb*64*HW + y*W + x0 + tx*4;
    #pragma unroll
    for (int o = 0; o < 8; o++) {
        int oc = ty*8 + o;
        float bi = __ldg(&dcn_b[oc]);
        float2 f0 = upk2(acc2[o][0]);
        float2 f1 = upk2(acc2[o][1]);
        float4 r;
        r.x = f0.x + bi; r.y = f0.y + bi; r.z = f1.x + bi; r.w = f1.y + bi;
        *(float4*)(ob + (size_t)oc*HW) = r;
    }
}

// ---------------- launch ----------------
extern "C" void kernel_launch(void* const* d_in, const int* in_sizes, int n_in,
                              void* d_out, int out_size) {
    const float* x       = (const float*)d_in[0];
    const float* init_w  = (const float*)d_in[1];
    const float* init_b  = (const float*)d_in[2];
    const float* prelu_a = (const float*)d_in[3];
    const float* offm_w  = (const float*)d_in[4];
    const float* offm_b  = (const float*)d_in[5];
    const float* dcn_w   = (const float*)d_in[6];
    const float* dcn_b   = (const float*)d_in[7];
    float* out = (float*)d_out;

    wprep_kernel<<<(9*64*64 + 255)/256, 256>>>(dcn_w);
    whprep_kernel<<<(2*64*9*32 + 255)/256, 256>>>(offm_w);
    init_conv_kernel<<<dim3(64, 10), 256>>>(x, init_w, init_b, prelu_a);
    transpose_kernel<<<dim3(256, 10), 256>>>();
    half_conv_kernel<<<dim3(64, 12), 128>>>();
    dcn_kernel<<<dim3(256, 10), 128>>>(offm_b, dcn_b, out);
}

// round 12
// speedup vs baseline: 1.3126x; 1.3126x over previous
#include <cuda_runtime.h>
#include <stdint.h>
#include <math.h>

#define H 128
#define W 128
#define HW (H*W)
#define NF 64
#define TT 5
#define BB 2

// ---------------- scratch ----------------
__device__ float g_feats[BB*TT*NF*HW];       // NCHW
__device__ float g_fnhwc[BB*TT*HW*NF];       // NHWC
__device__ float g_half[BB*6*27*HW];
__device__ float g_wt[9*64*64];              // dcn weights [k][c][o]
__device__ float g_hw[2*64*9*32];            // half-conv weights [icg][c][tap][slot], slot=q*8+i, oc=q*7+i

// ---------------- f32x2 helpers ----------------
typedef unsigned long long ull;
__device__ __forceinline__ ull pk2(float lo, float hi) {
    ull r; asm("mov.b64 %0, {%1,%2};" : "=l"(r) : "f"(lo), "f"(hi)); return r;
}
__device__ __forceinline__ void ffma2(ull& d, ull a, ull b) {
    asm("fma.rn.f32x2 %0, %1, %2, %0;" : "+l"(d) : "l"(a), "l"(b));
}
__device__ __forceinline__ float2 upk2(ull v) {
    float2 f; asm("mov.b64 {%0,%1}, %2;" : "=f"(f.x), "=f"(f.y) : "l"(v)); return f;
}
__device__ __forceinline__ void cp_async4(uint32_t saddr, const float* g, bool pred) {
    int bytes = pred ? 4 : 0;
    asm volatile("cp.async.ca.shared.global [%0], [%1], 4, %2;" :: "r"(saddr), "l"(g), "r"(bytes));
}
__device__ __forceinline__ void cp_async16(uint32_t saddr, const float* g, bool pred) {
    int bytes = pred ? 16 : 0;
    asm volatile("cp.async.ca.shared.global [%0], [%1], 16, %2;" :: "r"(saddr), "l"(g), "r"(bytes));
}

// ---------------- W-prep: dcn weights (all 36864) ----------------
__global__ void wprep_kernel(const float* __restrict__ dcn_w) {
    int i = blockIdx.x * blockDim.x + threadIdx.x;
    if (i >= 9*64*64) return;
    int o = i & 63;
    int c = (i >> 6) & 63;
    int k = i >> 12;
    g_wt[i] = dcn_w[(o*64 + c)*9 + k];
}

// ---------------- W-prep: half-conv weights into staged layout ----------------
__global__ void whprep_kernel(const float* __restrict__ offm_w) {
    int i = blockIdx.x * blockDim.x + threadIdx.x;
    if (i >= 2*64*9*32) return;
    int slot = i & 31;
    int rest = i >> 5;             // (icg*64 + c)*9 + tap
    int tap = rest % 9;
    int cc  = rest / 9;            // icg*64 + c, 0..127
    int qq = slot >> 3, ii = slot & 7;
    int oc = qq*7 + ii;
    float v = 0.f;
    if (ii < 7 && oc < 27) v = offm_w[(oc*128 + cc)*9 + tap];
    g_hw[i] = v;
}

// ---------------- kernel A: 3->64 conv3x3 + bias + PReLU -> NCHW only ----------------
__global__ void __launch_bounds__(256) init_conv_kernel(
    const float* __restrict__ x, const float* __restrict__ wgt,
    const float* __restrict__ bias, const float* __restrict__ prelu_a)
{
    __shared__ float sx[3][18][18];
    __shared__ __align__(8) float sw[27*64];
    __shared__ __align__(8) float sb[64];
    int tid = threadIdx.x;
    int n = blockIdx.y;
    int ty0 = (blockIdx.x >> 3) * 16;
    int tx0 = (blockIdx.x & 7) * 16;

    for (int idx = tid; idx < 1728; idx += 256) {
        int oc = idx & 63;
        int r = idx >> 6;
        int ic = r / 9, tap = r % 9;
        sw[idx] = wgt[(oc*3 + ic)*9 + tap];
    }
    if (tid < 64) sb[tid] = bias[tid];

    const float* xin = x + n*3*HW;
    for (int idx = tid; idx < 3*18*18; idx += 256) {
        int c = idx / 324;
        int r = (idx / 18) % 18;
        int col = idx % 18;
        int gy = ty0 + r - 1, gx = tx0 + col - 1;
        float v = 0.f;
        if (gy >= 0 && gy < H && gx >= 0 && gx < W) v = xin[c*HW + gy*W + gx];
        sx[c][r][col] = v;
    }
    __syncthreads();

    int ly = tid >> 4, lx = tid & 15;
    ull acc2[32];
    #pragma unroll
    for (int o2 = 0; o2 < 32; o2++) acc2[o2] = *(const ull*)&sb[2*o2];

    for (int ic = 0; ic < 3; ic++) {
        #pragma unroll
        for (int tap = 0; tap < 9; tap++) {
            int dy = tap / 3, dx = tap % 3;
            float v = sx[ic][ly + dy][lx + dx];
            ull v2 = pk2(v, v);
            const ull* wp = (const ull*)&sw[(ic*9 + tap)*64];
            #pragma unroll
            for (int o2 = 0; o2 < 32; o2++) ffma2(acc2[o2], v2, wp[o2]);
        }
    }
    float a = prelu_a[0];
    int pix = (ty0 + ly)*W + (tx0 + lx);
    float* dst = g_feats + (size_t)n*NF*HW + pix;
    #pragma unroll
    for (int o2 = 0; o2 < 32; o2++) {
        float2 f = upk2(acc2[o2]);
        dst[(2*o2)*HW]   = (f.x > 0.f) ? f.x : a*f.x;
        dst[(2*o2+1)*HW] = (f.y > 0.f) ? f.y : a*f.y;
    }
}

// ---------------- transpose NCHW -> NHWC ----------------
__global__ void __launch_bounds__(256) transpose_kernel()
{
    __shared__ float tile[64][65];
    int tid = threadIdx.x;
    int n = blockIdx.y;
    int px0 = blockIdx.x * 64;
    const float* src = g_feats + (size_t)n*NF*HW + px0;
    float* dst = g_fnhwc + ((size_t)n*HW + px0)*64;

    #pragma unroll
    for (int i = 0; i < 16; i++) {
        int idx = tid + i*256;
        int c = idx >> 6, xx = idx & 63;
        tile[c][xx] = src[c*HW + xx];
    }
    __syncthreads();
    #pragma unroll
    for (int i = 0; i < 16; i++) {
        int idx = tid + i*256;
        int p = idx >> 6, c = idx & 63;
        dst[p*64 + c] = tile[c][p];
    }
}

// ---------------- kernel B v6: half offset-conv, 8 px/thread, LDS.128 weights ----------------
// 128 threads: q = tid>>5 (oc quarter, warp-uniform); lane: ly=lane>>2 (row), lx=lane&3 (8-px group)
// tile 8 rows x 32 cols; cp.async double-buffered; weights prestaged via g_hw
__global__ void __launch_bounds__(128, 4) half_conv_kernel()
{
    __shared__ __align__(16) float st[2][8][10][44];   // [buf][c][row][col]; interior cols 4..35, halo 3/36
    __shared__ __align__(16) float ws[2][2304];        // [buf][(c*9+tap)*32 + slot]
    int tid = threadIdx.x;
    int task = blockIdx.y;
    int b = task / 6, s = task % 6;
    int tsel = (s == 0) ? 0 : (s - 1);
    int icg  = (s == 0) ? 0 : 1;
    int y0 = (blockIdx.x >> 2) * 8;
    int x0 = (blockIdx.x & 3) * 32;

    const float* src  = g_feats + (size_t)((b*TT + tsel)*NF)*HW;
    const float* wsrc = g_hw + icg*64*9*32;

    int q    = tid >> 5;
    int lane = tid & 31;
    int ly   = lane >> 2;
    int lx   = lane & 3;

    uint32_t st_sm = (uint32_t)__cvta_generic_to_shared(&st[0][0][0][0]);
    uint32_t ws_sm = (uint32_t)__cvta_generic_to_shared(&ws[0][0]);
    const uint32_t ST_BUF = 8*10*44*4;
    const uint32_t WS_BUF = 2304*4;

    auto stage = [&](int icb, int buf) {
        uint32_t stb = st_sm + buf*ST_BUF;
        // interior: 8c x 10rows x 8 segs of 4 floats
        for (int idx = tid; idx < 640; idx += 128) {
            int c = idx / 80;
            int rem = idx % 80;
            int rr = rem >> 3, seg = rem & 7;
            int gy = y0 + rr - 1;
            bool p = (gy >= 0) && (gy < H);
            const float* g = src + (icb + c)*HW + (p ? gy : 0)*W + x0 + seg*4;
            cp_async16(stb + (((c*10 + rr)*44) + 4 + seg*4)*4, g, p);
        }
        // halo: 8c x 10rows x 2 sides
        for (int idx = tid; idx < 160; idx += 128) {
            int c = idx / 20;
            int rem = idx % 20;
            int rr = rem >> 1, side = rem & 1;
            int gy = y0 + rr - 1;
            int gx = side ? (x0 + 32) : (x0 - 1);
            bool p = (gy >= 0) && (gy < H) && (gx >= 0) && (gx < W);
            int col = side ? 36 : 3;
            cp_async4(stb + (((c*10 + rr)*44) + col)*4, src + (icb + c)*HW + (p ? gy*W + gx : 0), p);
        }
        // weights: contiguous 2304 floats = 576 x 16B
        uint32_t wsb = ws_sm + buf*WS_BUF;
        const float* base = wsrc + icb*9*32;
        for (int idx = tid; idx < 576; idx += 128) {
            cp_async16(wsb + idx*16, base + idx*4, true);
        }
    };

    ull acc2[4][8];
    #pragma unroll
    for (int o2 = 0; o2 < 4; o2++)
        #pragma unroll
        for (int p = 0; p < 8; p++) acc2[o2][p] = 0ULL;

    stage(0, 0);
    asm volatile("cp.async.commit_group;");

    for (int ci = 0; ci < 8; ci++) {
        int buf = ci & 1;
        if (ci < 7) {
            stage((ci + 1)*8, buf ^ 1);
            asm volatile("cp.async.commit_group;");
            asm volatile("cp.async.wait_group 1;");
        } else {
            asm volatile("cp.async.wait_group 0;");
        }
        __syncthreads();

        const float (*stb)[10][44] = st[buf];
        const float* wsb = ws[buf];
        int cb = 4 + 8*lx;

        #pragma unroll
        for (int c = 0; c < 8; c++) {
            #pragma unroll
            for (int dy = 0; dy < 3; dy++) {
                const float* rp = &stb[c][ly + dy][0];
                float4 a  = *(const float4*)(rp + cb);
                float4 bb = *(const float4*)(rp + cb + 4);
                float hl = rp[cb - 1], hr = rp[cb + 8];
                ull iv[10];
                iv[0] = pk2(hl, hl);
                iv[1] = pk2(a.x, a.x);  iv[2] = pk2(a.y, a.y);
                iv[3] = pk2(a.z, a.z);  iv[4] = pk2(a.w, a.w);
                iv[5] = pk2(bb.x, bb.x); iv[6] = pk2(bb.y, bb.y);
                iv[7] = pk2(bb.z, bb.z); iv[8] = pk2(bb.w, bb.w);
                iv[9] = pk2(hr, hr);
                #pragma unroll
                for (int dx = 0; dx < 3; dx++) {
                    const ulonglong2* wp = (const ulonglong2*)&wsb[(c*9 + dy*3 + dx)*32 + q*8];
                    ulonglong2 wA = wp[0];
                    ulonglong2 wB = wp[1];
                    #pragma unroll
                    for (int p = 0; p < 8; p++) {
                        ull v = iv[p + dx];
                        ffma2(acc2[0][p], v, wA.x);
                        ffma2(acc2[1][p], v, wA.y);
                        ffma2(acc2[2][p], v, wB.x);
                        ffma2(acc2[3][p], v, wB.y);
                    }
                }
            }
        }
        __syncthreads();   // release buf for stage at ci+2
    }

    // epilogue: 7 real oc per quarter, 8 px -> 2x STG.128 each
    float* dst = g_half + (size_t)(task*27)*HW + (y0 + ly)*W + x0 + 8*lx;
    #pragma unroll
    for (int i = 0; i < 7; i++) {
        int oc = q*7 + i;
        if (oc >= 27) break;
        float4 lo, hi;
        float* lv = (float*)&lo;
        float* hv = (float*)&hi;
        #pragma unroll
        for (int p = 0; p < 4; p++) {
            float2 f = upk2(acc2[i >> 1][p]);
            lv[p] = (i & 1) ? f.y : f.x;
        }
        #pragma unroll
        for (int p = 4; p < 8; p++) {
            float2 f = upk2(acc2[i >> 1][p]);
            hv[p - 4] = (i & 1) ? f.y : f.x;
        }
        *(float4*)(dst + (size_t)oc*HW) = lo;
        *(float4*)(dst + (size_t)oc*HW + 4) = hi;
    }
}

// ---------------- kernel C: dcn (R5-proven), 64oc x 128px, 4 blocks/SM ----------------
__global__ void __launch_bounds__(128, 4) dcn_kernel(
    const float* __restrict__ offm_b, const float* __restrict__ dcn_b,
    float* __restrict__ out)
{
    extern __shared__ __align__(16) float smem[];
    float* S   = smem;                                 // [c][128], 8-px blocks xor-swizzled
    float* Wt  = smem + 64*128;                        // [c][o]
    int*   sAi = (int*)(smem + 64*128 + 64*64);        // [4][128]
    float* sWm = (float*)(sAi + 4*128);                // [4][128]

    int tid = threadIdx.x;
    int jb = blockIdx.y;
    int j = jb >> 1, b = jb & 1;
    int y = blockIdx.x;

    const float* fb = g_fnhwc + (size_t)(b*TT + j)*HW*64;
    const float* h0 = g_half + (size_t)((b*6 + 0)*27)*HW;
    const float* h1 = g_half + (size_t)((b*6 + 1 + j)*27)*HW;

    int tx = tid & 15;
    int ty = tid >> 4;

    ull acc2[8][4];
    #pragma unroll
    for (int o = 0; o < 8; o++)
        #pragma unroll
        for (int p = 0; p < 4; p++) acc2[o][p] = 0ULL;

    for (int k = 0; k < 9; k++) {
        __syncthreads();

        #pragma unroll
        for (int i = 0; i < 32; i++) Wt[tid + i*128] = g_wt[k*4096 + tid + i*128];

        {
            int gx = tid;
            int pix = y*W + gx;
            float oy = h0[k*HW + pix] + h1[k*HW + pix] + offm_b[k];
            float ox = h0[(9+k)*HW + pix] + h1[(9+k)*HW + pix] + offm_b[9+k];
            float mm = h0[(18+k)*HW + pix] + h1[(18+k)*HW + pix] + offm_b[18+k];
            float mask = 1.f / (1.f + expf(-mm));
            float py  = (float)(y + (k/3) - 1) + oy;
            float pxf = (float)(gx + (k%3) - 1) + ox;
            float y0f = floorf(py), x0f = floorf(pxf);
            float lyf = py - y0f, lxf = pxf - x0f;
            int yi = (int)y0f, xi = (int)x0f;
            bool vy0 = (yi >= 0) & (yi < H);
            bool vy1 = (yi >= -1) & (yi < H-1);
            bool vx0 = (xi >= 0) & (xi < W);
            bool vx1 = (xi >= -1) & (xi < W-1);
            int yc0 = min(max(yi, 0), H-1);
            int yc1 = min(max(yi+1, 0), H-1);
            int xc0 = min(max(xi, 0), W-1);
            int xc1 = min(max(xi+1, 0), W-1);
            float wy0 = 1.f - lyf, wy1 = lyf, wx0 = 1.f - lxf, wx1 = lxf;
            sAi[0*128 + tid] = (yc0*W + xc0) * 64;  sWm[0*128 + tid] = (vy0 && vx0) ? wy0*wx0*mask : 0.f;
            sAi[1*128 + tid] = (yc0*W + xc1) * 64;  sWm[1*128 + tid] = (vy0 && vx1) ? wy0*wx1*mask : 0.f;
            sAi[2*128 + tid] = (yc1*W + xc0) * 64;  sWm[2*128 + tid] = (vy1 && vx0) ? wy1*wx0*mask : 0.f;
            sAi[3*128 + tid] = (yc1*W + xc1) * 64;  sWm[3*128 + tid] = (vy1 && vx1) ? wy1*wx1*mask : 0.f;
        }
        __syncthreads();

        #pragma unroll
        for (int it = 0; it < 8; it++) {
            int task = tid + it*128;
            int px = task >> 3;
            int qq = task & 7;
            int a0 = sAi[0*128 + px], a1 = sAi[1*128 + px];
            int a2 = sAi[2*128 + px], a3 = sAi[3*128 + px];
            float w0 = sWm[0*128 + px], w1 = sWm[1*128 + px];
            float w2 = sWm[2*128 + px], w3 = sWm[3*128 + px];
            int blk = px >> 3, pof = px & 7;
            #pragma unroll
            for (int i = 0; i < 2; i++) {
                int ch4 = qq + i*8;
                float4 v0 = *(const float4*)(fb + a0 + ch4*4);
                float4 v1 = *(const float4*)(fb + a1 + ch4*4);
                float4 v2 = *(const float4*)(fb + a2 + ch4*4);
                float4 v3 = *(const float4*)(fb + a3 + ch4*4);
                float4 r;
                r.x = fmaf(w3, v3.x, fmaf(w2, v2.x, fmaf(w1, v1.x, w0*v0.x)));
                r.y = fmaf(w3, v3.y, fmaf(w2, v2.y, fmaf(w1, v1.y, w0*v0.y)));
                r.z = fmaf(w3, v3.z, fmaf(w2, v2.z, fmaf(w1, v1.z, w0*v0.z)));
                r.w = fmaf(w3, v3.w, fmaf(w2, v2.w, fmaf(w1, v1.w, w0*v0.w)));
                int xb = ((blk ^ (ch4 & 3)) << 3) + pof;
                int c0 = ch4*4;
                S[(c0+0)*128 + xb] = r.x;
                S[(c0+1)*128 + xb] = r.y;
                S[(c0+2)*128 + xb] = r.z;
                S[(c0+3)*128 + xb] = r.w;
            }
        }
        __syncthreads();

        #pragma unroll 4
        for (int kk = 0; kk < 64; kk++) {
            float4 wA0 = *(const float4*)&Wt[kk*64 + ty*8];
            float4 wA1 = *(const float4*)&Wt[kk*64 + ty*8 + 4];
            int xb = (tx ^ ((kk >> 2) & 3)) << 3;
            const ull* bp = (const ull*)&S[kk*128 + xb];
            ull b0 = bp[0], b1 = bp[1], b2 = bp[2], b3 = bp[3];
            ull sv;
            sv = pk2(wA0.x, wA0.x); ffma2(acc2[0][0], sv, b0); ffma2(acc2[0][1], sv, b1); ffma2(acc2[0][2], sv, b2); ffma2(acc2[0][3], sv, b3);
            sv = pk2(wA0.y, wA0.y); ffma2(acc2[1][0], sv, b0); ffma2(acc2[1][1], sv, b1); ffma2(acc2[1][2], sv, b2); ffma2(acc2[1][3], sv, b3);
            sv = pk2(wA0.z, wA0.z); ffma2(acc2[2][0], sv, b0); ffma2(acc2[2][1], sv, b1); ffma2(acc2[2][2], sv, b2); ffma2(acc2[2][3], sv, b3);
            sv = pk2(wA0.w, wA0.w); ffma2(acc2[3][0], sv, b0); ffma2(acc2[3][1], sv, b1); ffma2(acc2[3][2], sv, b2); ffma2(acc2[3][3], sv, b3);
            sv = pk2(wA1.x, wA1.x); ffma2(acc2[4][0], sv, b0); ffma2(acc2[4][1], sv, b1); ffma2(acc2[4][2], sv, b2); ffma2(acc2[4][3], sv, b3);
            sv = pk2(wA1.y, wA1.y); ffma2(acc2[5][0], sv, b0); ffma2(acc2[5][1], sv, b1); ffma2(acc2[5][2], sv, b2); ffma2(acc2[5][3], sv, b3);
            sv = pk2(wA1.z, wA1.z); ffma2(acc2[6][0], sv, b0); ffma2(acc2[6][1], sv, b1); ffma2(acc2[6][2], sv, b2); ffma2(acc2[6][3], sv, b3);
            sv = pk2(wA1.w, wA1.w); ffma2(acc2[7][0], sv, b0); ffma2(acc2[7][1], sv, b1); ffma2(acc2[7][2], sv, b2); ffma2(acc2[7][3], sv, b3);
        }
    }

    float* ob = out + (size_t)jb*64*HW + y*W + tx*8;
    #pragma unroll
    for (int o = 0; o < 8; o++) {
        int oc = ty*8 + o;
        float bi = __ldg(&dcn_b[oc]);
        float2 f0 = upk2(acc2[o][0]);
        float2 f1 = upk2(acc2[o][1]);
        float2 f2 = upk2(acc2[o][2]);
        float2 f3 = upk2(acc2[o][3]);
        float4 lo, hi;
        lo.x = f0.x + bi; lo.y = f0.y + bi; lo.z = f1.x + bi; lo.w = f1.y + bi;
        hi.x = f2.x + bi; hi.y = f2.y + bi; hi.z = f3.x + bi; hi.w = f3.y + bi;
        *(float4*)(ob + (size_t)oc*HW) = lo;
        *(float4*)(ob + (size_t)oc*HW + 4) = hi;
    }
}

// ---------------- launch ----------------
extern "C" void kernel_launch(void* const* d_in, const int* in_sizes, int n_in,
                              void* d_out, int out_size) {
    const float* x       = (const float*)d_in[0];
    const float* init_w  = (const float*)d_in[1];
    const float* init_b  = (const float*)d_in[2];
    const float* prelu_a = (const float*)d_in[3];
    const float* offm_w  = (const float*)d_in[4];
    const float* offm_b  = (const float*)d_in[5];
    const float* dcn_w   = (const float*)d_in[6];
    const float* dcn_b   = (const float*)d_in[7];
    float* out = (float*)d_out;

    static bool attr_set = false;
    if (!attr_set) {
        cudaFuncSetAttribute(dcn_kernel, cudaFuncAttributeMaxDynamicSharedMemorySize, 53248);
        attr_set = true;
    }

    wprep_kernel<<<(9*64*64 + 255)/256, 256>>>(dcn_w);
    whprep_kernel<<<(2*64*9*32 + 255)/256, 256>>>(offm_w);
    init_conv_kernel<<<dim3(64, 10), 256>>>(x, init_w, init_b, prelu_a);
    transpose_kernel<<<dim3(256, 10), 256>>>();
    half_conv_kernel<<<dim3(64, 12), 128>>>();
    dcn_kernel<<<dim3(128, 10), 128, 53248>>>(offm_b, dcn_b, out);
}

// round 13
// speedup vs baseline: 1.8926x; 1.4419x over previous
#include <cuda_runtime.h>
#include <cuda_fp16.h>
#include <stdint.h>
#include <math.h>

#define H 128
#define W 128
#define HW (H*W)
#define NF 64
#define TT 5
#define BB 2

// ---------------- scratch ----------------
__device__ float g_feats[BB*TT*NF*HW];       // NCHW
__device__ float g_fnhwc[BB*TT*HW*NF];       // NHWC
__device__ float g_half[BB*6*27*HW];
__device__ __half g_wth[9*64*64];            // dcn weights fp16, [k][o][swizzled-c]
__device__ float g_hw[2*64*9*32];            // half-conv weights [icg][c][tap][slot]

// ---------------- f32x2 helpers ----------------
typedef unsigned long long ull;
__device__ __forceinline__ ull pk2(float lo, float hi) {
    ull r; asm("mov.b64 %0, {%1,%2};" : "=l"(r) : "f"(lo), "f"(hi)); return r;
}
__device__ __forceinline__ void ffma2(ull& d, ull a, ull b) {
    asm("fma.rn.f32x2 %0, %1, %2, %0;" : "+l"(d) : "l"(a), "l"(b));
}
__device__ __forceinline__ float2 upk2(ull v) {
    float2 f; asm("mov.b64 {%0,%1}, %2;" : "=f"(f.x), "=f"(f.y) : "l"(v)); return f;
}
__device__ __forceinline__ void cp_async4(uint32_t saddr, const float* g, bool pred) {
    int bytes = pred ? 4 : 0;
    asm volatile("cp.async.ca.shared.global [%0], [%1], 4, %2;" :: "r"(saddr), "l"(g), "r"(bytes));
}
__device__ __forceinline__ void cp_async16(uint32_t saddr, const float* g, bool pred) {
    int bytes = pred ? 16 : 0;
    asm volatile("cp.async.ca.shared.global [%0], [%1], 16, %2;" :: "r"(saddr), "l"(g), "r"(bytes));
}
__device__ __forceinline__ void mma16816(float* d, const uint32_t* a, const uint32_t* b) {
    asm volatile(
        "mma.sync.aligned.m16n8k16.row.col.f32.f16.f16.f32 "
        "{%0,%1,%2,%3},{%4,%5,%6,%7},{%8,%9},{%0,%1,%2,%3};"
        : "+f"(d[0]), "+f"(d[1]), "+f"(d[2]), "+f"(d[3])
        : "r"(a[0]), "r"(a[1]), "r"(a[2]), "r"(a[3]), "r"(b[0]), "r"(b[1]));
}

// ---------------- W-prep: dcn weights -> fp16 swizzled [k][o][c'] ----------------
__global__ void wth_prep_kernel(const float* __restrict__ dcn_w) {
    int i = blockIdx.x * blockDim.x + threadIdx.x;
    if (i >= 9*64*64) return;
    int k = i >> 12;
    int rest = i & 4095;
    int o = rest >> 6;
    int c = rest & 63;
    int u = c >> 3;
    int pos = (((u ^ (o & 7)) << 3) | (c & 7));
    g_wth[k*4096 + o*64 + pos] = __float2half(dcn_w[(o*64 + c)*9 + k]);
}

// ---------------- W-prep: half-conv weights into staged layout ----------------
__global__ void whprep_kernel(const float* __restrict__ offm_w) {
    int i = blockIdx.x * blockDim.x + threadIdx.x;
    if (i >= 2*64*9*32) return;
    int slot = i & 31;
    int rest = i >> 5;
    int tap = rest % 9;
    int cc  = rest / 9;
    int qq = slot >> 3, ii = slot & 7;
    int oc = qq*7 + ii;
    float v = 0.f;
    if (ii < 7 && oc < 27) v = offm_w[(oc*128 + cc)*9 + tap];
    g_hw[i] = v;
}

// ---------------- kernel A: 3->64 conv3x3 + bias + PReLU -> NCHW only ----------------
__global__ void __launch_bounds__(256) init_conv_kernel(
    const float* __restrict__ x, const float* __restrict__ wgt,
    const float* __restrict__ bias, const float* __restrict__ prelu_a)
{
    __shared__ float sx[3][18][18];
    __shared__ __align__(8) float sw[27*64];
    __shared__ __align__(8) float sb[64];
    int tid = threadIdx.x;
    int n = blockIdx.y;
    int ty0 = (blockIdx.x >> 3) * 16;
    int tx0 = (blockIdx.x & 7) * 16;

    for (int idx = tid; idx < 1728; idx += 256) {
        int oc = idx & 63;
        int r = idx >> 6;
        int ic = r / 9, tap = r % 9;
        sw[idx] = wgt[(oc*3 + ic)*9 + tap];
    }
    if (tid < 64) sb[tid] = bias[tid];

    const float* xin = x + n*3*HW;
    for (int idx = tid; idx < 3*18*18; idx += 256) {
        int c = idx / 324;
        int r = (idx / 18) % 18;
        int col = idx % 18;
        int gy = ty0 + r - 1, gx = tx0 + col - 1;
        float v = 0.f;
        if (gy >= 0 && gy < H && gx >= 0 && gx < W) v = xin[c*HW + gy*W + gx];
        sx[c][r][col] = v;
    }
    __syncthreads();

    int ly = tid >> 4, lx = tid & 15;
    ull acc2[32];
    #pragma unroll
    for (int o2 = 0; o2 < 32; o2++) acc2[o2] = *(const ull*)&sb[2*o2];

    for (int ic = 0; ic < 3; ic++) {
        #pragma unroll
        for (int tap = 0; tap < 9; tap++) {
            int dy = tap / 3, dx = tap % 3;
            float v = sx[ic][ly + dy][lx + dx];
            ull v2 = pk2(v, v);
            const ull* wp = (const ull*)&sw[(ic*9 + tap)*64];
            #pragma unroll
            for (int o2 = 0; o2 < 32; o2++) ffma2(acc2[o2], v2, wp[o2]);
        }
    }
    float a = prelu_a[0];
    int pix = (ty0 + ly)*W + (tx0 + lx);
    float* dst = g_feats + (size_t)n*NF*HW + pix;
    #pragma unroll
    for (int o2 = 0; o2 < 32; o2++) {
        float2 f = upk2(acc2[o2]);
        dst[(2*o2)*HW]   = (f.x > 0.f) ? f.x : a*f.x;
        dst[(2*o2+1)*HW] = (f.y > 0.f) ? f.y : a*f.y;
    }
}

// ---------------- transpose NCHW -> NHWC ----------------
__global__ void __launch_bounds__(256) transpose_kernel()
{
    __shared__ float tile[64][65];
    int tid = threadIdx.x;
    int n = blockIdx.y;
    int px0 = blockIdx.x * 64;
    const float* src = g_feats + (size_t)n*NF*HW + px0;
    float* dst = g_fnhwc + ((size_t)n*HW + px0)*64;

    #pragma unroll
    for (int i = 0; i < 16; i++) {
        int idx = tid + i*256;
        int c = idx >> 6, xx = idx & 63;
        tile[c][xx] = src[c*HW + xx];
    }
    __syncthreads();
    #pragma unroll
    for (int i = 0; i < 16; i++) {
        int idx = tid + i*256;
        int p = idx >> 6, c = idx & 63;
        dst[p*64 + c] = tile[c][p];
    }
}

// ---------------- kernel B v6: half offset-conv (unchanged) ----------------
__global__ void __launch_bounds__(128, 4) half_conv_kernel()
{
    __shared__ __align__(16) float st[2][8][10][44];
    __shared__ __align__(16) float ws[2][2304];
    int tid = threadIdx.x;
    int task = blockIdx.y;
    int b = task / 6, s = task % 6;
    int tsel = (s == 0) ? 0 : (s - 1);
    int icg  = (s == 0) ? 0 : 1;
    int y0 = (blockIdx.x >> 2) * 8;
    int x0 = (blockIdx.x & 3) * 32;

    const float* src  = g_feats + (size_t)((b*TT + tsel)*NF)*HW;
    const float* wsrc = g_hw + icg*64*9*32;

    int q    = tid >> 5;
    int lane = tid & 31;
    int ly   = lane >> 2;
    int lx   = lane & 3;

    uint32_t st_sm = (uint32_t)__cvta_generic_to_shared(&st[0][0][0][0]);
    uint32_t ws_sm = (uint32_t)__cvta_generic_to_shared(&ws[0][0]);
    const uint32_t ST_BUF = 8*10*44*4;
    const uint32_t WS_BUF = 2304*4;

    auto stage = [&](int icb, int buf) {
        uint32_t stb = st_sm + buf*ST_BUF;
        for (int idx = tid; idx < 640; idx += 128) {
            int c = idx / 80;
            int rem = idx % 80;
            int rr = rem >> 3, seg = rem & 7;
            int gy = y0 + rr - 1;
            bool p = (gy >= 0) && (gy < H);
            const float* g = src + (icb + c)*HW + (p ? gy : 0)*W + x0 + seg*4;
            cp_async16(stb + (((c*10 + rr)*44) + 4 + seg*4)*4, g, p);
        }
        for (int idx = tid; idx < 160; idx += 128) {
            int c = idx / 20;
            int rem = idx % 20;
            int rr = rem >> 1, side = rem & 1;
            int gy = y0 + rr - 1;
            int gx = side ? (x0 + 32) : (x0 - 1);
            bool p = (gy >= 0) && (gy < H) && (gx >= 0) && (gx < W);
            int col = side ? 36 : 3;
            cp_async4(stb + (((c*10 + rr)*44) + col)*4, src + (icb + c)*HW + (p ? gy*W + gx : 0), p);
        }
        uint32_t wsb = ws_sm + buf*WS_BUF;
        const float* base = wsrc + icb*9*32;
        for (int idx = tid; idx < 576; idx += 128) {
            cp_async16(wsb + idx*16, base + idx*4, true);
        }
    };

    ull acc2[4][8];
    #pragma unroll
    for (int o2 = 0; o2 < 4; o2++)
        #pragma unroll
        for (int p = 0; p < 8; p++) acc2[o2][p] = 0ULL;

    stage(0, 0);
    asm volatile("cp.async.commit_group;");

    for (int ci = 0; ci < 8; ci++) {
        int buf = ci & 1;
        if (ci < 7) {
            stage((ci + 1)*8, buf ^ 1);
            asm volatile("cp.async.commit_group;");
            asm volatile("cp.async.wait_group 1;");
        } else {
            asm volatile("cp.async.wait_group 0;");
        }
        __syncthreads();

        const float (*stb)[10][44] = st[buf];
        const float* wsb = ws[buf];
        int cb = 4 + 8*lx;

        #pragma unroll
        for (int c = 0; c < 8; c++) {
            #pragma unroll
            for (int dy = 0; dy < 3; dy++) {
                const float* rp = &stb[c][ly + dy][0];
                float4 a  = *(const float4*)(rp + cb);
                float4 bb = *(const float4*)(rp + cb + 4);
                float hl = rp[cb - 1], hr = rp[cb + 8];
                ull iv[10];
                iv[0] = pk2(hl, hl);
                iv[1] = pk2(a.x, a.x);  iv[2] = pk2(a.y, a.y);
                iv[3] = pk2(a.z, a.z);  iv[4] = pk2(a.w, a.w);
                iv[5] = pk2(bb.x, bb.x); iv[6] = pk2(bb.y, bb.y);
                iv[7] = pk2(bb.z, bb.z); iv[8] = pk2(bb.w, bb.w);
                iv[9] = pk2(hr, hr);
                #pragma unroll
                for (int dx = 0; dx < 3; dx++) {
                    const ulonglong2* wp = (const ulonglong2*)&wsb[(c*9 + dy*3 + dx)*32 + q*8];
                    ulonglong2 wA = wp[0];
                    ulonglong2 wB = wp[1];
                    #pragma unroll
                    for (int p = 0; p < 8; p++) {
                        ull v = iv[p + dx];
                        ffma2(acc2[0][p], v, wA.x);
                        ffma2(acc2[1][p], v, wA.y);
                        ffma2(acc2[2][p], v, wB.x);
                        ffma2(acc2[3][p], v, wB.y);
                    }
                }
            }
        }
        __syncthreads();
    }

    float* dst = g_half + (size_t)(task*27)*HW + (y0 + ly)*W + x0 + 8*lx;
    #pragma unroll
    for (int i = 0; i < 7; i++) {
        int oc = q*7 + i;
        if (oc >= 27) break;
        float4 lo, hi;
        float* lv = (float*)&lo;
        float* hv = (float*)&hi;
        #pragma unroll
        for (int p = 0; p < 4; p++) {
            float2 f = upk2(acc2[i >> 1][p]);
            lv[p] = (i & 1) ? f.y : f.x;
        }
        #pragma unroll
        for (int p = 4; p < 8; p++) {
            float2 f = upk2(acc2[i >> 1][p]);
            hv[p - 4] = (i & 1) ? f.y : f.x;
        }
        *(float4*)(dst + (size_t)oc*HW) = lo;
        *(float4*)(dst + (size_t)oc*HW + 4) = hi;
    }
}

// ---------------- kernel C v4: dcn with HMMA fp16 tensor cores ----------------
// 128 threads (4 warps); tile 64oc x 128px, one row y per block.
// A = W_h [oc][c] fp16 swizzled; B = S_h [px][c] fp16 swizzled; D = [oc][px] fp32.
// Warp w covers px [w*32, w*32+32); m-tiles: 4x16 oc; n-tiles: 4x8 px; K=64 per tap.
__global__ void __launch_bounds__(128, 4) dcn_kernel(
    const float* __restrict__ offm_b, const float* __restrict__ dcn_b,
    float* __restrict__ out)
{
    __shared__ __align__(16) __half S_h[128*64];   // 16 KB, row = px (128 B), swizzle u^(px&7)
    __shared__ __align__(16) __half W_h[64*64];    // 8 KB, row = oc (128 B), swizzle u^(o&7)
    __shared__ int   sAi[4][128];
    __shared__ float sWm[4][128];

    int tid = threadIdx.x;
    int jb = blockIdx.y;
    int j = jb >> 1, b = jb & 1;
    int y = blockIdx.x;

    const float* fb = g_fnhwc + (size_t)(b*TT + j)*HW*64;
    const float* h0 = g_half + (size_t)((b*6 + 0)*27)*HW;
    const float* h1 = g_half + (size_t)((b*6 + 1 + j)*27)*HW;

    int lane = tid & 31;
    int warp = tid >> 5;
    int r4 = lane >> 2;       // 0..7
    int c2 = lane & 3;        // 0..3
    int w32 = warp * 32;      // warp's px base

    float acc[4][4][4];       // [m-tile][n-tile][frag]
    #pragma unroll
    for (int mt = 0; mt < 4; mt++)
        #pragma unroll
        for (int nt = 0; nt < 4; nt++)
            #pragma unroll
            for (int f = 0; f < 4; f++) acc[mt][nt][f] = 0.f;

    char* Sb = (char*)S_h;
    char* Wb = (char*)W_h;

    for (int k = 0; k < 9; k++) {
        __syncthreads();   // prev GEMM done reading S_h/W_h

        // stage W_h for this tap (8 KB, contiguous copy; swizzle prebaked in g_wth)
        {
            const float4* src4 = (const float4*)(g_wth + k*4096);
            float4* dst4 = (float4*)W_h;
            #pragma unroll
            for (int i = 0; i < 4; i++) dst4[tid + i*128] = src4[tid + i*128];
        }

        // per-pixel meta (one px per thread)
        {
            int gx = tid;
            int pix = y*W + gx;
            float oy = h0[k*HW + pix] + h1[k*HW + pix] + offm_b[k];
            float ox = h0[(9+k)*HW + pix] + h1[(9+k)*HW + pix] + offm_b[9+k];
            float mm = h0[(18+k)*HW + pix] + h1[(18+k)*HW + pix] + offm_b[18+k];
            float mask = 1.f / (1.f + expf(-mm));
            float py  = (float)(y + (k/3) - 1) + oy;
            float pxf = (float)(gx + (k%3) - 1) + ox;
            float y0f = floorf(py), x0f = floorf(pxf);
            float lyf = py - y0f, lxf = pxf - x0f;
            int yi = (int)y0f, xi = (int)x0f;
            bool vy0 = (yi >= 0) & (yi < H);
            bool vy1 = (yi >= -1) & (yi < H-1);
            bool vx0 = (xi >= 0) & (xi < W);
            bool vx1 = (xi >= -1) & (xi < W-1);
            int yc0 = min(max(yi, 0), H-1);
            int yc1 = min(max(yi+1, 0), H-1);
            int xc0 = min(max(xi, 0), W-1);
            int xc1 = min(max(xi+1, 0), W-1);
            float wy0 = 1.f - lyf, wy1 = lyf, wx0 = 1.f - lxf, wx1 = lxf;
            sAi[0][tid] = (yc0*W + xc0) * 64;  sWm[0][tid] = (vy0 && vx0) ? wy0*wx0*mask : 0.f;
            sAi[1][tid] = (yc0*W + xc1) * 64;  sWm[1][tid] = (vy0 && vx1) ? wy0*wx1*mask : 0.f;
            sAi[2][tid] = (yc1*W + xc0) * 64;  sWm[2][tid] = (vy1 && vx0) ? wy1*wx0*mask : 0.f;
            sAi[3][tid] = (yc1*W + xc1) * 64;  sWm[3][tid] = (vy1 && vx1) ? wy1*wx1*mask : 0.f;
        }
        __syncthreads();

        // gather: 1024 tasks = 128 px * 8 channel-lanes; combine fp32, store half2x2
        #pragma unroll
        for (int it = 0; it < 8; it++) {
            int task = tid + it*128;
            int px = task >> 3;
            int qq = task & 7;
            int a0 = sAi[0][px], a1 = sAi[1][px];
            int a2 = sAi[2][px], a3 = sAi[3][px];
            float w0 = sWm[0][px], w1 = sWm[1][px];
            float w2 = sWm[2][px], w3 = sWm[3][px];
            #pragma unroll
            for (int i = 0; i < 2; i++) {
                int ch4 = qq + i*8;
                float4 v0 = *(const float4*)(fb + a0 + ch4*4);
                float4 v1 = *(const float4*)(fb + a1 + ch4*4);
                float4 v2 = *(const float4*)(fb + a2 + ch4*4);
                float4 v3 = *(const float4*)(fb + a3 + ch4*4);
                float4 r;
                r.x = fmaf(w3, v3.x, fmaf(w2, v2.x, fmaf(w1, v1.x, w0*v0.x)));
                r.y = fmaf(w3, v3.y, fmaf(w2, v2.y, fmaf(w1, v1.y, w0*v0.y)));
                r.z = fmaf(w3, v3.z, fmaf(w2, v2.z, fmaf(w1, v1.z, w0*v0.z)));
                r.w = fmaf(w3, v3.w, fmaf(w2, v2.w, fmaf(w1, v1.w, w0*v0.w)));
                __half2 h01 = __float22half2_rn(make_float2(r.x, r.y));
                __half2 h23 = __float22half2_rn(make_float2(r.z, r.w));
                uint2 pkv;
                pkv.x = *(uint32_t*)&h01;
                pkv.y = *(uint32_t*)&h23;
                int u = ch4 >> 1;
                int byteoff = px*128 + (((u ^ (px & 7)) << 4) | ((ch4 & 1) << 3));
                *(uint2*)(Sb + byteoff) = pkv;
            }
        }
        __syncthreads();

        // HMMA GEMM: K=64 in 4 k16 steps
        #pragma unroll
        for (int ks = 0; ks < 4; ks++) {
            int u0 = (ks*2) ^ r4;
            int u1 = (ks*2 + 1) ^ r4;
            int bo0 = (u0 << 4) | (c2 << 2);
            int bo1 = (u1 << 4) | (c2 << 2);

            uint32_t afr[4][4];
            #pragma unroll
            for (int mt = 0; mt < 4; mt++) {
                char* wr = Wb + (mt*16 + r4)*128;
                afr[mt][0] = *(uint32_t*)(wr + bo0);
                afr[mt][1] = *(uint32_t*)(wr + 8*128 + bo0);
                afr[mt][2] = *(uint32_t*)(wr + bo1);
                afr[mt][3] = *(uint32_t*)(wr + 8*128 + bo1);
            }
            uint32_t bfr[4][2];
            #pragma unroll
            for (int nt = 0; nt < 4; nt++) {
                char* sr = Sb + (w32 + nt*8 + r4)*128;
                bfr[nt][0] = *(uint32_t*)(sr + bo0);
                bfr[nt][1] = *(uint32_t*)(sr + bo1);
            }
            #pragma unroll
            for (int mt = 0; mt < 4; mt++)
                #pragma unroll
                for (int nt = 0; nt < 4; nt++)
                    mma16816(acc[mt][nt], afr[mt], bfr[nt]);
        }
    }

    // epilogue: D[oc][px] frags -> out, bias in fp32
    #pragma unroll
    for (int mt = 0; mt < 4; mt++) {
        int oc = mt*16 + r4;
        float bi0 = __ldg(&dcn_b[oc]);
        float bi8 = __ldg(&dcn_b[oc + 8]);
        #pragma unroll
        for (int nt = 0; nt < 4; nt++) {
            int px = w32 + nt*8 + c2*2;
            float* o0 = out + ((size_t)jb*64 + oc)*HW + y*W + px;
            float* o8 = out + ((size_t)jb*64 + oc + 8)*HW + y*W + px;
            float2 v0, v1;
            v0.x = acc[mt][nt][0] + bi0; v0.y = acc[mt][nt][1] + bi0;
            v1.x = acc[mt][nt][2] + bi8; v1.y = acc[mt][nt][3] + bi8;
            *(float2*)o0 = v0;
            *(float2*)o8 = v1;
        }
    }
}

// ---------------- launch ----------------
extern "C" void kernel_launch(void* const* d_in, const int* in_sizes, int n_in,
                              void* d_out, int out_size) {
    const float* x       = (const float*)d_in[0];
    const float* init_w  = (const float*)d_in[1];
    const float* init_b  = (const float*)d_in[2];
    const float* prelu_a = (const float*)d_in[3];
    const float* offm_w  = (const float*)d_in[4];
    const float* offm_b  = (const float*)d_in[5];
    const float* dcn_w   = (const float*)d_in[6];
    const float* dcn_b   = (const float*)d_in[7];
    float* out = (float*)d_out;

    wth_prep_kernel<<<(9*64*64 + 255)/256, 256>>>(dcn_w);
    whprep_kernel<<<(2*64*9*32 + 255)/256, 256>>>(offm_w);
    init_conv_kernel<<<dim3(64, 10), 256>>>(x, init_w, init_b, prelu_a);
    transpose_kernel<<<dim3(256, 10), 256>>>();
    half_conv_kernel<<<dim3(64, 12), 128>>>();
    dcn_kernel<<<dim3(128, 10), 128>>>(offm_b, dcn_b, out);
}

// round 14
// speedup vs baseline: 2.1863x; 1.1552x over previous
#include <cuda_runtime.h>
#include <cuda_fp16.h>
#include <stdint.h>
#include <math.h>

#define H 128
#define W 128
#define HW (H*W)
#define NF 64
#define TT 5
#define BB 2

// ---------------- scratch ----------------
__device__ float g_feats[BB*TT*NF*HW];       // NCHW fp32
__device__ __half g_fnhwc_h[BB*TT*HW*NF];    // NHWC fp16
__device__ float g_half[BB*6*27*HW];
__device__ __half g_wth[9*64*64];            // dcn weights fp16, [k][o][swizzled-c]
__device__ float g_hw[2*64*9*32];            // half-conv weights [icg][c][tap][slot]

// ---------------- f32x2 helpers ----------------
typedef unsigned long long ull;
__device__ __forceinline__ ull pk2(float lo, float hi) {
    ull r; asm("mov.b64 %0, {%1,%2};" : "=l"(r) : "f"(lo), "f"(hi)); return r;
}
__device__ __forceinline__ void ffma2(ull& d, ull a, ull b) {
    asm("fma.rn.f32x2 %0, %1, %2, %0;" : "+l"(d) : "l"(a), "l"(b));
}
__device__ __forceinline__ float2 upk2(ull v) {
    float2 f; asm("mov.b64 {%0,%1}, %2;" : "=f"(f.x), "=f"(f.y) : "l"(v)); return f;
}
__device__ __forceinline__ void cp_async4(uint32_t saddr, const float* g, bool pred) {
    int bytes = pred ? 4 : 0;
    asm volatile("cp.async.ca.shared.global [%0], [%1], 4, %2;" :: "r"(saddr), "l"(g), "r"(bytes));
}
__device__ __forceinline__ void cp_async16(uint32_t saddr, const float* g, bool pred) {
    int bytes = pred ? 16 : 0;
    asm volatile("cp.async.ca.shared.global [%0], [%1], 16, %2;" :: "r"(saddr), "l"(g), "r"(bytes));
}
__device__ __forceinline__ void mma16816(float* d, const uint32_t* a, const uint32_t* b) {
    asm volatile(
        "mma.sync.aligned.m16n8k16.row.col.f32.f16.f16.f32 "
        "{%0,%1,%2,%3},{%4,%5,%6,%7},{%8,%9},{%0,%1,%2,%3};"
        : "+f"(d[0]), "+f"(d[1]), "+f"(d[2]), "+f"(d[3])
        : "r"(a[0]), "r"(a[1]), "r"(a[2]), "r"(a[3]), "r"(b[0]), "r"(b[1]));
}

// ---------------- W-prep: dcn weights -> fp16 swizzled [k][o][c'] ----------------
__global__ void wth_prep_kernel(const float* __restrict__ dcn_w) {
    int i = blockIdx.x * blockDim.x + threadIdx.x;
    if (i >= 9*64*64) return;
    int k = i >> 12;
    int rest = i & 4095;
    int o = rest >> 6;
    int c = rest & 63;
    int u = c >> 3;
    int pos = (((u ^ (o & 7)) << 3) | (c & 7));
    g_wth[k*4096 + o*64 + pos] = __float2half(dcn_w[(o*64 + c)*9 + k]);
}

// ---------------- W-prep: half-conv weights into staged layout ----------------
__global__ void whprep_kernel(const float* __restrict__ offm_w) {
    int i = blockIdx.x * blockDim.x + threadIdx.x;
    if (i >= 2*64*9*32) return;
    int slot = i & 31;
    int rest = i >> 5;
    int tap = rest % 9;
    int cc  = rest / 9;
    int qq = slot >> 3, ii = slot & 7;
    int oc = qq*7 + ii;
    float v = 0.f;
    if (ii < 7 && oc < 27) v = offm_w[(oc*128 + cc)*9 + tap];
    g_hw[i] = v;
}

// ---------------- kernel A: 3->64 conv3x3 + bias + PReLU -> NCHW only ----------------
__global__ void __launch_bounds__(256) init_conv_kernel(
    const float* __restrict__ x, const float* __restrict__ wgt,
    const float* __restrict__ bias, const float* __restrict__ prelu_a)
{
    __shared__ float sx[3][18][18];
    __shared__ __align__(8) float sw[27*64];
    __shared__ __align__(8) float sb[64];
    int tid = threadIdx.x;
    int n = blockIdx.y;
    int ty0 = (blockIdx.x >> 3) * 16;
    int tx0 = (blockIdx.x & 7) * 16;

    for (int idx = tid; idx < 1728; idx += 256) {
        int oc = idx & 63;
        int r = idx >> 6;
        int ic = r / 9, tap = r % 9;
        sw[idx] = wgt[(oc*3 + ic)*9 + tap];
    }
    if (tid < 64) sb[tid] = bias[tid];

    const float* xin = x + n*3*HW;
    for (int idx = tid; idx < 3*18*18; idx += 256) {
        int c = idx / 324;
        int r = (idx / 18) % 18;
        int col = idx % 18;
        int gy = ty0 + r - 1, gx = tx0 + col - 1;
        float v = 0.f;
        if (gy >= 0 && gy < H && gx >= 0 && gx < W) v = xin[c*HW + gy*W + gx];
        sx[c][r][col] = v;
    }
    __syncthreads();

    int ly = tid >> 4, lx = tid & 15;
    ull acc2[32];
    #pragma unroll
    for (int o2 = 0; o2 < 32; o2++) acc2[o2] = *(const ull*)&sb[2*o2];

    for (int ic = 0; ic < 3; ic++) {
        #pragma unroll
        for (int tap = 0; tap < 9; tap++) {
            int dy = tap / 3, dx = tap % 3;
            float v = sx[ic][ly + dy][lx + dx];
            ull v2 = pk2(v, v);
            const ull* wp = (const ull*)&sw[(ic*9 + tap)*64];
            #pragma unroll
            for (int o2 = 0; o2 < 32; o2++) ffma2(acc2[o2], v2, wp[o2]);
        }
    }
    float a = prelu_a[0];
    int pix = (ty0 + ly)*W + (tx0 + lx);
    float* dst = g_feats + (size_t)n*NF*HW + pix;
    #pragma unroll
    for (int o2 = 0; o2 < 32; o2++) {
        float2 f = upk2(acc2[o2]);
        dst[(2*o2)*HW]   = (f.x > 0.f) ? f.x : a*f.x;
        dst[(2*o2+1)*HW] = (f.y > 0.f) ? f.y : a*f.y;
    }
}

// ---------------- transpose NCHW fp32 -> NHWC fp16 ----------------
__global__ void __launch_bounds__(256) transpose_kernel()
{
    __shared__ float tile[64][65];
    int tid = threadIdx.x;
    int n = blockIdx.y;
    int px0 = blockIdx.x * 64;
    const float* src = g_feats + (size_t)n*NF*HW + px0;
    __half2* dst = (__half2*)(g_fnhwc_h + ((size_t)n*HW + px0)*64);

    #pragma unroll
    for (int i = 0; i < 16; i++) {
        int idx = tid + i*256;
        int c = idx >> 6, xx = idx & 63;
        tile[c][xx] = src[c*HW + xx];
    }
    __syncthreads();
    // 64 px * 32 half2-pairs = 2048 stores of 4B, coalesced
    #pragma unroll
    for (int i = 0; i < 8; i++) {
        int idx = tid + i*256;
        int p = idx >> 5;
        int c2 = idx & 31;
        float2 f;
        f.x = tile[c2*2][p];
        f.y = tile[c2*2 + 1][p];
        dst[p*32 + c2] = __float22half2_rn(f);
    }
}

// ---------------- kernel B v6: half offset-conv (unchanged) ----------------
__global__ void __launch_bounds__(128, 4) half_conv_kernel()
{
    __shared__ __align__(16) float st[2][8][10][44];
    __shared__ __align__(16) float ws[2][2304];
    int tid = threadIdx.x;
    int task = blockIdx.y;
    int b = task / 6, s = task % 6;
    int tsel = (s == 0) ? 0 : (s - 1);
    int icg  = (s == 0) ? 0 : 1;
    int y0 = (blockIdx.x >> 2) * 8;
    int x0 = (blockIdx.x & 3) * 32;

    const float* src  = g_feats + (size_t)((b*TT + tsel)*NF)*HW;
    const float* wsrc = g_hw + icg*64*9*32;

    int q    = tid >> 5;
    int lane = tid & 31;
    int ly   = lane >> 2;
    int lx   = lane & 3;

    uint32_t st_sm = (uint32_t)__cvta_generic_to_shared(&st[0][0][0][0]);
    uint32_t ws_sm = (uint32_t)__cvta_generic_to_shared(&ws[0][0]);
    const uint32_t ST_BUF = 8*10*44*4;
    const uint32_t WS_BUF = 2304*4;

    auto stage = [&](int icb, int buf) {
        uint32_t stb = st_sm + buf*ST_BUF;
        for (int idx = tid; idx < 640; idx += 128) {
            int c = idx / 80;
            int rem = idx % 80;
            int rr = rem >> 3, seg = rem & 7;
            int gy = y0 + rr - 1;
            bool p = (gy >= 0) && (gy < H);
            const float* g = src + (icb + c)*HW + (p ? gy : 0)*W + x0 + seg*4;
            cp_async16(stb + (((c*10 + rr)*44) + 4 + seg*4)*4, g, p);
        }
        for (int idx = tid; idx < 160; idx += 128) {
            int c = idx / 20;
            int rem = idx % 20;
            int rr = rem >> 1, side = rem & 1;
            int gy = y0 + rr - 1;
            int gx = side ? (x0 + 32) : (x0 - 1);
            bool p = (gy >= 0) && (gy < H) && (gx >= 0) && (gx < W);
            int col = side ? 36 : 3;
            cp_async4(stb + (((c*10 + rr)*44) + col)*4, src + (icb + c)*HW + (p ? gy*W + gx : 0), p);
        }
        uint32_t wsb = ws_sm + buf*WS_BUF;
        const float* base = wsrc + icb*9*32;
        for (int idx = tid; idx < 576; idx += 128) {
            cp_async16(wsb + idx*16, base + idx*4, true);
        }
    };

    ull acc2[4][8];
    #pragma unroll
    for (int o2 = 0; o2 < 4; o2++)
        #pragma unroll
        for (int p = 0; p < 8; p++) acc2[o2][p] = 0ULL;

    stage(0, 0);
    asm volatile("cp.async.commit_group;");

    for (int ci = 0; ci < 8; ci++) {
        int buf = ci & 1;
        if (ci < 7) {
            stage((ci + 1)*8, buf ^ 1);
            asm volatile("cp.async.commit_group;");
            asm volatile("cp.async.wait_group 1;");
        } else {
            asm volatile("cp.async.wait_group 0;");
        }
        __syncthreads();

        const float (*stb)[10][44] = st[buf];
        const float* wsb = ws[buf];
        int cb = 4 + 8*lx;

        #pragma unroll
        for (int c = 0; c < 8; c++) {
            #pragma unroll
            for (int dy = 0; dy < 3; dy++) {
                const float* rp = &stb[c][ly + dy][0];
                float4 a  = *(const float4*)(rp + cb);
                float4 bb = *(const float4*)(rp + cb + 4);
                float hl = rp[cb - 1], hr = rp[cb + 8];
                ull iv[10];
                iv[0] = pk2(hl, hl);
                iv[1] = pk2(a.x, a.x);  iv[2] = pk2(a.y, a.y);
                iv[3] = pk2(a.z, a.z);  iv[4] = pk2(a.w, a.w);
                iv[5] = pk2(bb.x, bb.x); iv[6] = pk2(bb.y, bb.y);
                iv[7] = pk2(bb.z, bb.z); iv[8] = pk2(bb.w, bb.w);
                iv[9] = pk2(hr, hr);
                #pragma unroll
                for (int dx = 0; dx < 3; dx++) {
                    const ulonglong2* wp = (const ulonglong2*)&wsb[(c*9 + dy*3 + dx)*32 + q*8];
                    ulonglong2 wA = wp[0];
                    ulonglong2 wB = wp[1];
                    #pragma unroll
                    for (int p = 0; p < 8; p++) {
                        ull v = iv[p + dx];
                        ffma2(acc2[0][p], v, wA.x);
                        ffma2(acc2[1][p], v, wA.y);
                        ffma2(acc2[2][p], v, wB.x);
                        ffma2(acc2[3][p], v, wB.y);
                    }
                }
            }
        }
        __syncthreads();
    }

    float* dst = g_half + (size_t)(task*27)*HW + (y0 + ly)*W + x0 + 8*lx;
    #pragma unroll
    for (int i = 0; i < 7; i++) {
        int oc = q*7 + i;
        if (oc >= 27) break;
        float4 lo, hi;
        float* lv = (float*)&lo;
        float* hv = (float*)&hi;
        #pragma unroll
        for (int p = 0; p < 4; p++) {
            float2 f = upk2(acc2[i >> 1][p]);
            lv[p] = (i & 1) ? f.y : f.x;
        }
        #pragma unroll
        for (int p = 4; p < 8; p++) {
            float2 f = upk2(acc2[i >> 1][p]);
            hv[p - 4] = (i & 1) ? f.y : f.x;
        }
        *(float4*)(dst + (size_t)oc*HW) = lo;
        *(float4*)(dst + (size_t)oc*HW + 4) = hi;
    }
}

// ---------------- kernel C v5: dcn HMMA, fp16 feature gather ----------------
// 128 threads (4 warps); tile 64oc x 128px, one row y per block.
__global__ void __launch_bounds__(128, 4) dcn_kernel(
    const float* __restrict__ offm_b, const float* __restrict__ dcn_b,
    float* __restrict__ out)
{
    __shared__ __align__(16) __half S_h[128*64];   // 16 KB, row = px (128 B), 16B unit u ^ (px&7)
    __shared__ __align__(16) __half W_h[64*64];    // 8 KB
    __shared__ int   sAi[4][128];
    __shared__ float sWm[4][128];

    int tid = threadIdx.x;
    int jb = blockIdx.y;
    int j = jb >> 1, b = jb & 1;
    int y = blockIdx.x;

    const __half* fbh = g_fnhwc_h + (size_t)(b*TT + j)*HW*64;
    const float* h0 = g_half + (size_t)((b*6 + 0)*27)*HW;
    const float* h1 = g_half + (size_t)((b*6 + 1 + j)*27)*HW;

    int lane = tid & 31;
    int warp = tid >> 5;
    int r4 = lane >> 2;
    int c2 = lane & 3;
    int w32 = warp * 32;

    float acc[4][4][4];
    #pragma unroll
    for (int mt = 0; mt < 4; mt++)
        #pragma unroll
        for (int nt = 0; nt < 4; nt++)
            #pragma unroll
            for (int f = 0; f < 4; f++) acc[mt][nt][f] = 0.f;

    char* Sb = (char*)S_h;
    char* Wb = (char*)W_h;

    for (int k = 0; k < 9; k++) {
        __syncthreads();

        // stage W_h for this tap
        {
            const float4* src4 = (const float4*)(g_wth + k*4096);
            float4* dst4 = (float4*)W_h;
            #pragma unroll
            for (int i = 0; i < 4; i++) dst4[tid + i*128] = src4[tid + i*128];
        }

        // per-pixel meta
        {
            int gx = tid;
            int pix = y*W + gx;
            float oy = h0[k*HW + pix] + h1[k*HW + pix] + offm_b[k];
            float ox = h0[(9+k)*HW + pix] + h1[(9+k)*HW + pix] + offm_b[9+k];
            float mm = h0[(18+k)*HW + pix] + h1[(18+k)*HW + pix] + offm_b[18+k];
            float mask = 1.f / (1.f + expf(-mm));
            float py  = (float)(y + (k/3) - 1) + oy;
            float pxf = (float)(gx + (k%3) - 1) + ox;
            float y0f = floorf(py), x0f = floorf(pxf);
            float lyf = py - y0f, lxf = pxf - x0f;
            int yi = (int)y0f, xi = (int)x0f;
            bool vy0 = (yi >= 0) & (yi < H);
            bool vy1 = (yi >= -1) & (yi < H-1);
            bool vx0 = (xi >= 0) & (xi < W);
            bool vx1 = (xi >= -1) & (xi < W-1);
            int yc0 = min(max(yi, 0), H-1);
            int yc1 = min(max(yi+1, 0), H-1);
            int xc0 = min(max(xi, 0), W-1);
            int xc1 = min(max(xi+1, 0), W-1);
            float wy0 = 1.f - lyf, wy1 = lyf, wx0 = 1.f - lxf, wx1 = lxf;
            sAi[0][tid] = (yc0*W + xc0) * 64;  sWm[0][tid] = (vy0 && vx0) ? wy0*wx0*mask : 0.f;
            sAi[1][tid] = (yc0*W + xc1) * 64;  sWm[1][tid] = (vy0 && vx1) ? wy0*wx1*mask : 0.f;
            sAi[2][tid] = (yc1*W + xc0) * 64;  sWm[2][tid] = (vy1 && vx0) ? wy1*wx0*mask : 0.f;
            sAi[3][tid] = (yc1*W + xc1) * 64;  sWm[3][tid] = (vy1 && vx1) ? wy1*wx1*mask : 0.f;
        }
        __syncthreads();

        // gather: 1024 tasks = 128 px * 8 ch8-lanes; 4x uint4 fp16 loads, combine fp32, 1x STS.128
        #pragma unroll
        for (int it = 0; it < 8; it++) {
            int task = tid + it*128;
            int px = task >> 3;
            int qq = task & 7;                 // ch8 group
            int a0 = sAi[0][px], a1 = sAi[1][px];
            int a2 = sAi[2][px], a3 = sAi[3][px];
            ull w0 = pk2(sWm[0][px], sWm[0][px]);
            ull w1 = pk2(sWm[1][px], sWm[1][px]);
            ull w2 = pk2(sWm[2][px], sWm[2][px]);
            ull w3 = pk2(sWm[3][px], sWm[3][px]);
            uint4 v0 = *(const uint4*)(fbh + a0 + qq*8);
            uint4 v1 = *(const uint4*)(fbh + a1 + qq*8);
            uint4 v2 = *(const uint4*)(fbh + a2 + qq*8);
            uint4 v3 = *(const uint4*)(fbh + a3 + qq*8);
            const uint32_t* p0 = (const uint32_t*)&v0;
            const uint32_t* p1 = (const uint32_t*)&v1;
            const uint32_t* p2 = (const uint32_t*)&v2;
            const uint32_t* p3 = (const uint32_t*)&v3;
            uint4 outv;
            uint32_t* po = (uint32_t*)&outv;
            #pragma unroll
            for (int i = 0; i < 4; i++) {
                float2 f0 = __half22float2(*(const __half2*)&p0[i]);
                float2 f1 = __half22float2(*(const __half2*)&p1[i]);
                float2 f2 = __half22float2(*(const __half2*)&p2[i]);
                float2 f3 = __half22float2(*(const __half2*)&p3[i]);
                ull r = 0ULL;
                ffma2(r, w0, pk2(f0.x, f0.y));
                ffma2(r, w1, pk2(f1.x, f1.y));
                ffma2(r, w2, pk2(f2.x, f2.y));
                ffma2(r, w3, pk2(f3.x, f3.y));
                float2 rf = upk2(r);
                __half2 h = __float22half2_rn(rf);
                po[i] = *(uint32_t*)&h;
            }
            int byteoff = px*128 + ((qq ^ (px & 7)) << 4);
            *(uint4*)(Sb + byteoff) = outv;
        }
        __syncthreads();

        // HMMA GEMM: K=64 in 4 k16 steps
        #pragma unroll
        for (int ks = 0; ks < 4; ks++) {
            int u0 = (ks*2) ^ r4;
            int u1 = (ks*2 + 1) ^ r4;
            int bo0 = (u0 << 4) | (c2 << 2);
            int bo1 = (u1 << 4) | (c2 << 2);

            uint32_t afr[4][4];
            #pragma unroll
            for (int mt = 0; mt < 4; mt++) {
                char* wr = Wb + (mt*16 + r4)*128;
                afr[mt][0] = *(uint32_t*)(wr + bo0);
                afr[mt][1] = *(uint32_t*)(wr + 8*128 + bo0);
                afr[mt][2] = *(uint32_t*)(wr + bo1);
                afr[mt][3] = *(uint32_t*)(wr + 8*128 + bo1);
            }
            uint32_t bfr[4][2];
            #pragma unroll
            for (int nt = 0; nt < 4; nt++) {
                char* sr = Sb + (w32 + nt*8 + r4)*128;
                bfr[nt][0] = *(uint32_t*)(sr + bo0);
                bfr[nt][1] = *(uint32_t*)(sr + bo1);
            }
            #pragma unroll
            for (int mt = 0; mt < 4; mt++)
                #pragma unroll
                for (int nt = 0; nt < 4; nt++)
                    mma16816(acc[mt][nt], afr[mt], bfr[nt]);
        }
    }

    // epilogue
    #pragma unroll
    for (int mt = 0; mt < 4; mt++) {
        int oc = mt*16 + r4;
        float bi0 = __ldg(&dcn_b[oc]);
        float bi8 = __ldg(&dcn_b[oc + 8]);
        #pragma unroll
        for (int nt = 0; nt < 4; nt++) {
            int px = w32 + nt*8 + c2*2;
            float* o0 = out + ((size_t)jb*64 + oc)*HW + y*W + px;
            float* o8 = out + ((size_t)jb*64 + oc + 8)*HW + y*W + px;
            float2 v0, v1;
            v0.x = acc[mt][nt][0] + bi0; v0.y = acc[mt][nt][1] + bi0;
            v1.x = acc[mt][nt][2] + bi8; v1.y = acc[mt][nt][3] + bi8;
            *(float2*)o0 = v0;
            *(float2*)o8 = v1;
        }
    }
}

// ---------------- launch ----------------
extern "C" void kernel_launch(void* const* d_in, const int* in_sizes, int n_in,
                              void* d_out, int out_size) {
    const float* x       = (const float*)d_in[0];
    const float* init_w  = (const float*)d_in[1];
    const float* init_b  = (const float*)d_in[2];
    const float* prelu_a = (const float*)d_in[3];
    const float* offm_w  = (const float*)d_in[4];
    const float* offm_b  = (const float*)d_in[5];
    const float* dcn_w   = (const float*)d_in[6];
    const float* dcn_b   = (const float*)d_in[7];
    float* out = (float*)d_out;

    wth_prep_kernel<<<(9*64*64 + 255)/256, 256>>>(dcn_w);
    whprep_kernel<<<(2*64*9*32 + 255)/256, 256>>>(offm_w);
    init_conv_kernel<<<dim3(64, 10), 256>>>(x, init_w, init_b, prelu_a);
    transpose_kernel<<<dim3(256, 10), 256>>>();
    half_conv_kernel<<<dim3(64, 12), 128>>>();
    dcn_kernel<<<dim3(128, 10), 128>>>(offm_b, dcn_b, out);
}

// round 15
// speedup vs baseline: 3.0345x; 1.3879x over previous
#include <cuda_runtime.h>
#include <cuda_fp16.h>
#include <stdint.h>
#include <math.h>

#define H 128
#define W 128
#define HW (H*W)
#define NF 64
#define TT 5
#define BB 2

// ---------------- scratch ----------------
__device__ __half g_fnhwc_h[BB*TT*HW*NF];    // NHWC fp16 features
__device__ float g_half[BB*6*27*HW];         // half offset-conv outputs (fp32)
__device__ __half g_wth[9*64*64];            // dcn weights fp16, [k][o][swizzled-c]
__device__ __half g_hwh[2*9*32*64];          // half-conv weights fp16, [icg][tap][oc(pad32)][c]

// ---------------- helpers ----------------
typedef unsigned long long ull;
__device__ __forceinline__ ull pk2(float lo, float hi) {
    ull r; asm("mov.b64 %0, {%1,%2};" : "=l"(r) : "f"(lo), "f"(hi)); return r;
}
__device__ __forceinline__ void ffma2(ull& d, ull a, ull b) {
    asm("fma.rn.f32x2 %0, %1, %2, %0;" : "+l"(d) : "l"(a), "l"(b));
}
__device__ __forceinline__ float2 upk2(ull v) {
    float2 f; asm("mov.b64 {%0,%1}, %2;" : "=f"(f.x), "=f"(f.y) : "l"(v)); return f;
}
__device__ __forceinline__ void mma16816(float* d, const uint32_t* a, const uint32_t* b) {
    asm volatile(
        "mma.sync.aligned.m16n8k16.row.col.f32.f16.f16.f32 "
        "{%0,%1,%2,%3},{%4,%5,%6,%7},{%8,%9},{%0,%1,%2,%3};"
        : "+f"(d[0]), "+f"(d[1]), "+f"(d[2]), "+f"(d[3])
        : "r"(a[0]), "r"(a[1]), "r"(a[2]), "r"(a[3]), "r"(b[0]), "r"(b[1]));
}

// ---------------- W-prep: dcn weights -> fp16 swizzled [k][o][c'] ----------------
__global__ void wth_prep_kernel(const float* __restrict__ dcn_w) {
    int i = blockIdx.x * blockDim.x + threadIdx.x;
    if (i >= 9*64*64) return;
    int k = i >> 12;
    int rest = i & 4095;
    int o = rest >> 6;
    int c = rest & 63;
    int u = c >> 3;
    int pos = (((u ^ (o & 7)) << 3) | (c & 7));
    g_wth[k*4096 + o*64 + pos] = __float2half(dcn_w[(o*64 + c)*9 + k]);
}

// ---------------- W-prep: half-conv weights fp16 [icg][tap][oc32][c] linear ----------------
__global__ void hwh_prep_kernel(const float* __restrict__ offm_w) {
    int i = blockIdx.x * blockDim.x + threadIdx.x;
    if (i >= 2*9*32*64) return;
    int c = i & 63;
    int r = i >> 6;
    int oc = r & 31; r >>= 5;
    int tap = r % 9;
    int icg = r / 9;
    float v = 0.f;
    if (oc < 27) v = offm_w[(oc*128 + icg*64 + c)*9 + tap];
    g_hwh[i] = __float2half(v);
}

// ---------------- kernel A: 3->64 conv3x3 + bias + PReLU -> NHWC fp16 directly ----------------
__global__ void __launch_bounds__(256) init_conv_kernel(
    const float* __restrict__ x, const float* __restrict__ wgt,
    const float* __restrict__ bias, const float* __restrict__ prelu_a)
{
    __shared__ float sx[3][18][18];
    __shared__ __align__(8) float sw[27*64];
    __shared__ __align__(8) float sb[64];
    int tid = threadIdx.x;
    int n = blockIdx.y;
    int ty0 = (blockIdx.x >> 3) * 16;
    int tx0 = (blockIdx.x & 7) * 16;

    for (int idx = tid; idx < 1728; idx += 256) {
        int oc = idx & 63;
        int r = idx >> 6;
        int ic = r / 9, tap = r % 9;
        sw[idx] = wgt[(oc*3 + ic)*9 + tap];
    }
    if (tid < 64) sb[tid] = bias[tid];

    const float* xin = x + n*3*HW;
    for (int idx = tid; idx < 3*18*18; idx += 256) {
        int c = idx / 324;
        int r = (idx / 18) % 18;
        int col = idx % 18;
        int gy = ty0 + r - 1, gx = tx0 + col - 1;
        float v = 0.f;
        if (gy >= 0 && gy < H && gx >= 0 && gx < W) v = xin[c*HW + gy*W + gx];
        sx[c][r][col] = v;
    }
    __syncthreads();

    int ly = tid >> 4, lx = tid & 15;
    ull acc2[32];
    #pragma unroll
    for (int o2 = 0; o2 < 32; o2++) acc2[o2] = *(const ull*)&sb[2*o2];

    for (int ic = 0; ic < 3; ic++) {
        #pragma unroll
        for (int tap = 0; tap < 9; tap++) {
            int dy = tap / 3, dx = tap % 3;
            float v = sx[ic][ly + dy][lx + dx];
            ull v2 = pk2(v, v);
            const ull* wp = (const ull*)&sw[(ic*9 + tap)*64];
            #pragma unroll
            for (int o2 = 0; o2 < 32; o2++) ffma2(acc2[o2], v2, wp[o2]);
        }
    }
    float a = prelu_a[0];
    int pix = (ty0 + ly)*W + (tx0 + lx);
    __half* nd = g_fnhwc_h + ((size_t)n*HW + pix)*64;
    #pragma unroll
    for (int g4 = 0; g4 < 8; g4++) {
        uint4 pkv;
        uint32_t* pp = (uint32_t*)&pkv;
        #pragma unroll
        for (int i = 0; i < 4; i++) {
            float2 f = upk2(acc2[g4*4 + i]);
            float h0v = (f.x > 0.f) ? f.x : a*f.x;
            float h1v = (f.y > 0.f) ? f.y : a*f.y;
            __half2 h = __float22half2_rn(make_float2(h0v, h1v));
            pp[i] = *(uint32_t*)&h;
        }
        *(uint4*)(nd + g4*8) = pkv;
    }
}

// ---------------- kernel B v7: half offset-conv via HMMA ----------------
// 128 threads (4 warps); block = one row y, 128 px, one task (b,s).
// Input tile staged once: 3 planes (y-1..y+1) x 130 px-rows (t=px+dx, x=t-1) x 64c fp16,
// swizzled 16B-unit u ^ (t&7). Per tap: A = g_hwh (broadcast __ldg), B = shifted smem rows.
__global__ void __launch_bounds__(128, 4) half_conv_kernel()
{
    extern __shared__ __align__(16) char Sb[];       // 3*132*128 bytes = 50688
    int tid = threadIdx.x;
    int task = blockIdx.y;
    int b = task / 6, s = task % 6;
    int tsel = (s == 0) ? 0 : (s - 1);
    int icg  = (s == 0) ? 0 : 1;
    int y = blockIdx.x;

    const __half* fbh = g_fnhwc_h + (size_t)(b*TT + tsel)*HW*64;
    const __half* wbase = g_hwh + (size_t)icg*9*32*64;

    // zero halo columns t=0 and t=129 (3 planes x 2 sides x 8 units)
    if (tid < 48) {
        int r = tid / 16;
        int side = (tid >> 3) & 1;
        int qq = tid & 7;
        int t = side ? 129 : 0;
        uint4 z = make_uint4(0, 0, 0, 0);
        *(uint4*)(Sb + (r*132 + t)*128 + ((qq ^ (t & 7)) << 4)) = z;
    }
    // interior: 3 planes x 128 t x 8 ch8-units
    #pragma unroll
    for (int i = 0; i < 24; i++) {
        int idx = tid + i*128;
        int r = idx >> 10;
        int rem = idx & 1023;
        int t = 1 + (rem >> 3);
        int qq = rem & 7;
        int gy = y + r - 1;
        uint4 v = make_uint4(0, 0, 0, 0);
        if (gy >= 0 && gy < H) v = *(const uint4*)(fbh + ((size_t)gy*W + (t - 1))*64 + qq*8);
        *(uint4*)(Sb + (r*132 + t)*128 + ((qq ^ (t & 7)) << 4)) = v;
    }
    __syncthreads();

    int lane = tid & 31;
    int warp = tid >> 5;
    int r4 = lane >> 2;
    int c2 = lane & 3;
    int w32 = warp * 32;

    float acc[2][4][4];
    #pragma unroll
    for (int mt = 0; mt < 2; mt++)
        #pragma unroll
        for (int nt = 0; nt < 4; nt++)
            #pragma unroll
            for (int f = 0; f < 4; f++) acc[mt][nt][f] = 0.f;

    #pragma unroll
    for (int tap = 0; tap < 9; tap++) {
        int dy = tap / 3, dx = tap % 3;
        const __half* wt = wbase + tap*2048;
        #pragma unroll
        for (int ks = 0; ks < 4; ks++) {
            uint32_t afr[2][4];
            #pragma unroll
            for (int mt = 0; mt < 2; mt++) {
                const __half* wr = wt + (mt*16 + r4)*64 + ks*16 + c2*2;
                afr[mt][0] = __ldg((const uint32_t*)wr);
                afr[mt][1] = __ldg((const uint32_t*)(wr + 512));
                afr[mt][2] = __ldg((const uint32_t*)(wr + 8));
                afr[mt][3] = __ldg((const uint32_t*)(wr + 520));
            }
            uint32_t bfr[4][2];
            #pragma unroll
            for (int nt = 0; nt < 4; nt++) {
                int t = w32 + nt*8 + r4 + dx;
                const char* sr = Sb + (dy*132 + t)*128;
                int tw = t & 7;
                bfr[nt][0] = *(const uint32_t*)(sr + (((ks*2) ^ tw) << 4) + (c2 << 2));
                bfr[nt][1] = *(const uint32_t*)(sr + (((ks*2 + 1) ^ tw) << 4) + (c2 << 2));
            }
            #pragma unroll
            for (int mt = 0; mt < 2; mt++)
                #pragma unroll
                for (int nt = 0; nt < 4; nt++)
                    mma16816(acc[mt][nt], afr[mt], bfr[nt]);
        }
    }

    // output: 27 real oc of 32, fp32
    float* dst = g_half + (size_t)task*27*HW + y*W;
    #pragma unroll
    for (int mt = 0; mt < 2; mt++) {
        int oc0 = mt*16 + r4;
        int oc1 = oc0 + 8;
        #pragma unroll
        for (int nt = 0; nt < 4; nt++) {
            int px = w32 + nt*8 + c2*2;
            if (oc0 < 27) {
                float2 v; v.x = acc[mt][nt][0]; v.y = acc[mt][nt][1];
                *(float2*)(dst + (size_t)oc0*HW + px) = v;
            }
            if (oc1 < 27) {
                float2 v; v.x = acc[mt][nt][2]; v.y = acc[mt][nt][3];
                *(float2*)(dst + (size_t)oc1*HW + px) = v;
            }
        }
    }
}

// ---------------- kernel C v5: dcn HMMA, fp16 feature gather (R14 verbatim) ----------------
__global__ void __launch_bounds__(128, 4) dcn_kernel(
    const float* __restrict__ offm_b, const float* __restrict__ dcn_b,
    float* __restrict__ out)
{
    __shared__ __align__(16) __half S_h[128*64];
    __shared__ __align__(16) __half W_h[64*64];
    __shared__ int   sAi[4][128];
    __shared__ float sWm[4][128];

    int tid = threadIdx.x;
    int jb = blockIdx.y;
    int j = jb >> 1, b = jb & 1;
    int y = blockIdx.x;

    const __half* fbh = g_fnhwc_h + (size_t)(b*TT + j)*HW*64;
    const float* h0 = g_half + (size_t)((b*6 + 0)*27)*HW;
    const float* h1 = g_half + (size_t)((b*6 + 1 + j)*27)*HW;

    int lane = tid & 31;
    int warp = tid >> 5;
    int r4 = lane >> 2;
    int c2 = lane & 3;
    int w32 = warp * 32;

    float acc[4][4][4];
    #pragma unroll
    for (int mt = 0; mt < 4; mt++)
        #pragma unroll
        for (int nt = 0; nt < 4; nt++)
            #pragma unroll
            for (int f = 0; f < 4; f++) acc[mt][nt][f] = 0.f;

    char* Sb = (char*)S_h;
    char* Wb = (char*)W_h;

    for (int k = 0; k < 9; k++) {
        __syncthreads();

        {
            const float4* src4 = (const float4*)(g_wth + k*4096);
            float4* dst4 = (float4*)W_h;
            #pragma unroll
            for (int i = 0; i < 4; i++) dst4[tid + i*128] = src4[tid + i*128];
        }

        {
            int gx = tid;
            int pix = y*W + gx;
            float oy = h0[k*HW + pix] + h1[k*HW + pix] + offm_b[k];
            float ox = h0[(9+k)*HW + pix] + h1[(9+k)*HW + pix] + offm_b[9+k];
            float mm = h0[(18+k)*HW + pix] + h1[(18+k)*HW + pix] + offm_b[18+k];
            float mask = 1.f / (1.f + expf(-mm));
            float py  = (float)(y + (k/3) - 1) + oy;
            float pxf = (float)(gx + (k%3) - 1) + ox;
            float y0f = floorf(py), x0f = floorf(pxf);
            float lyf = py - y0f, lxf = pxf - x0f;
            int yi = (int)y0f, xi = (int)x0f;
            bool vy0 = (yi >= 0) & (yi < H);
            bool vy1 = (yi >= -1) & (yi < H-1);
            bool vx0 = (xi >= 0) & (xi < W);
            bool vx1 = (xi >= -1) & (xi < W-1);
            int yc0 = min(max(yi, 0), H-1);
            int yc1 = min(max(yi+1, 0), H-1);
            int xc0 = min(max(xi, 0), W-1);
            int xc1 = min(max(xi+1, 0), W-1);
            float wy0 = 1.f - lyf, wy1 = lyf, wx0 = 1.f - lxf, wx1 = lxf;
            sAi[0][tid] = (yc0*W + xc0) * 64;  sWm[0][tid] = (vy0 && vx0) ? wy0*wx0*mask : 0.f;
            sAi[1][tid] = (yc0*W + xc1) * 64;  sWm[1][tid] = (vy0 && vx1) ? wy0*wx1*mask : 0.f;
            sAi[2][tid] = (yc1*W + xc0) * 64;  sWm[2][tid] = (vy1 && vx0) ? wy1*wx0*mask : 0.f;
            sAi[3][tid] = (yc1*W + xc1) * 64;  sWm[3][tid] = (vy1 && vx1) ? wy1*wx1*mask : 0.f;
        }
        __syncthreads();

        #pragma unroll
        for (int it = 0; it < 8; it++) {
            int task = tid + it*128;
            int px = task >> 3;
            int qq = task & 7;
            int a0 = sAi[0][px], a1 = sAi[1][px];
            int a2 = sAi[2][px], a3 = sAi[3][px];
            ull w0 = pk2(sWm[0][px], sWm[0][px]);
            ull w1 = pk2(sWm[1][px], sWm[1][px]);
            ull w2 = pk2(sWm[2][px], sWm[2][px]);
            ull w3 = pk2(sWm[3][px], sWm[3][px]);
            uint4 v0 = *(const uint4*)(fbh + a0 + qq*8);
            uint4 v1 = *(const uint4*)(fbh + a1 + qq*8);
            uint4 v2 = *(const uint4*)(fbh + a2 + qq*8);
            uint4 v3 = *(const uint4*)(fbh + a3 + qq*8);
            const uint32_t* p0 = (const uint32_t*)&v0;
            const uint32_t* p1 = (const uint32_t*)&v1;
            const uint32_t* p2 = (const uint32_t*)&v2;
            const uint32_t* p3 = (const uint32_t*)&v3;
            uint4 outv;
            uint32_t* po = (uint32_t*)&outv;
            #pragma unroll
            for (int i = 0; i < 4; i++) {
                float2 f0 = __half22float2(*(const __half2*)&p0[i]);
                float2 f1 = __half22float2(*(const __half2*)&p1[i]);
                float2 f2 = __half22float2(*(const __half2*)&p2[i]);
                float2 f3 = __half22float2(*(const __half2*)&p3[i]);
                ull r = 0ULL;
                ffma2(r, w0, pk2(f0.x, f0.y));
                ffma2(r, w1, pk2(f1.x, f1.y));
                ffma2(r, w2, pk2(f2.x, f2.y));
                ffma2(r, w3, pk2(f3.x, f3.y));
                float2 rf = upk2(r);
                __half2 h = __float22half2_rn(rf);
                po[i] = *(uint32_t*)&h;
            }
            int byteoff = px*128 + ((qq ^ (px & 7)) << 4);
            *(uint4*)(Sb + byteoff) = outv;
        }
        __syncthreads();

        #pragma unroll
        for (int ks = 0; ks < 4; ks++) {
            int u0 = (ks*2) ^ r4;
            int u1 = (ks*2 + 1) ^ r4;
            int bo0 = (u0 << 4) | (c2 << 2);
            int bo1 = (u1 << 4) | (c2 << 2);

            uint32_t afr[4][4];
            #pragma unroll
            for (int mt = 0; mt < 4; mt++) {
                char* wr = Wb + (mt*16 + r4)*128;
                afr[mt][0] = *(uint32_t*)(wr + bo0);
                afr[mt][1] = *(uint32_t*)(wr + 8*128 + bo0);
                afr[mt][2] = *(uint32_t*)(wr + bo1);
                afr[mt][3] = *(uint32_t*)(wr + 8*128 + bo1);
            }
            uint32_t bfr[4][2];
            #pragma unroll
            for (int nt = 0; nt < 4; nt++) {
                char* sr = Sb + (w32 + nt*8 + r4)*128;
                bfr[nt][0] = *(uint32_t*)(sr + bo0);
                bfr[nt][1] = *(uint32_t*)(sr + bo1);
            }
            #pragma unroll
            for (int mt = 0; mt < 4; mt++)
                #pragma unroll
                for (int nt = 0; nt < 4; nt++)
                    mma16816(acc[mt][nt], afr[mt], bfr[nt]);
        }
    }

    #pragma unroll
    for (int mt = 0; mt < 4; mt++) {
        int oc = mt*16 + r4;
        float bi0 = __ldg(&dcn_b[oc]);
        float bi8 = __ldg(&dcn_b[oc + 8]);
        #pragma unroll
        for (int nt = 0; nt < 4; nt++) {
            int px = w32 + nt*8 + c2*2;
            float* o0 = out + ((size_t)jb*64 + oc)*HW + y*W + px;
            float* o8 = out + ((size_t)jb*64 + oc + 8)*HW + y*W + px;
            float2 v0, v1;
            v0.x = acc[mt][nt][0] + bi0; v0.y = acc[mt][nt][1] + bi0;
            v1.x = acc[mt][nt][2] + bi8; v1.y = acc[mt][nt][3] + bi8;
            *(float2*)o0 = v0;
            *(float2*)o8 = v1;
        }
    }
}

// ---------------- launch ----------------
extern "C" void kernel_launch(void* const* d_in, const int* in_sizes, int n_in,
                              void* d_out, int out_size) {
    const float* x       = (const float*)d_in[0];
    const float* init_w  = (const float*)d_in[1];
    const float* init_b  = (const float*)d_in[2];
    const float* prelu_a = (const float*)d_in[3];
    const float* offm_w  = (const float*)d_in[4];
    const float* offm_b  = (const float*)d_in[5];
    const float* dcn_w   = (const float*)d_in[6];
    const float* dcn_b   = (const float*)d_in[7];
    float* out = (float*)d_out;

    static bool attr_set = false;
    if (!attr_set) {
        cudaFuncSetAttribute(half_conv_kernel, cudaFuncAttributeMaxDynamicSharedMemorySize, 50688);
        attr_set = true;
    }

    wth_prep_kernel<<<(9*64*64 + 255)/256, 256>>>(dcn_w);
    hwh_prep_kernel<<<(2*9*32*64 + 255)/256, 256>>>(offm_w);
    init_conv_kernel<<<dim3(64, 10), 256>>>(x, init_w, init_b, prelu_a);
    half_conv_kernel<<<dim3(128, 12), 128, 50688>>>();
    dcn_kernel<<<dim3(128, 10), 128>>>(offm_b, dcn_b, out);
}

// round 16
// speedup vs baseline: 3.7010x; 1.2196x over previous
#include <cuda_runtime.h>
#include <cuda_fp16.h>
#include <stdint.h>
#include <math.h>

#define H 128
#define W 128
#define HW (H*W)
#define NF 64
#define TT 5
#define BB 2

// ---------------- scratch ----------------
__device__ __half g_fnhwc_h[BB*TT*HW*NF];    // NHWC fp16 features
__device__ float g_half[BB*6*27*HW];         // half offset-conv outputs (fp32)
__device__ __half g_wth[9*64*64];            // dcn weights fp16, [k][o][swizzled-c]
__device__ __half g_hwh[2*9*32*64];          // half-conv weights fp16, [icg][tap][oc32][c-swizzled]

// ---------------- helpers ----------------
typedef unsigned long long ull;
__device__ __forceinline__ ull pk2(float lo, float hi) {
    ull r; asm("mov.b64 %0, {%1,%2};" : "=l"(r) : "f"(lo), "f"(hi)); return r;
}
__device__ __forceinline__ void ffma2(ull& d, ull a, ull b) {
    asm("fma.rn.f32x2 %0, %1, %2, %0;" : "+l"(d) : "l"(a), "l"(b));
}
__device__ __forceinline__ float2 upk2(ull v) {
    float2 f; asm("mov.b64 {%0,%1}, %2;" : "=f"(f.x), "=f"(f.y) : "l"(v)); return f;
}
__device__ __forceinline__ void cp_async16(uint32_t saddr, const void* g, bool pred) {
    int bytes = pred ? 16 : 0;
    asm volatile("cp.async.ca.shared.global [%0], [%1], 16, %2;" :: "r"(saddr), "l"(g), "r"(bytes));
}
__device__ __forceinline__ void mma16816(float* d, const uint32_t* a, const uint32_t* b) {
    asm volatile(
        "mma.sync.aligned.m16n8k16.row.col.f32.f16.f16.f32 "
        "{%0,%1,%2,%3},{%4,%5,%6,%7},{%8,%9},{%0,%1,%2,%3};"
        : "+f"(d[0]), "+f"(d[1]), "+f"(d[2]), "+f"(d[3])
        : "r"(a[0]), "r"(a[1]), "r"(a[2]), "r"(a[3]), "r"(b[0]), "r"(b[1]));
}
__device__ __forceinline__ void ldsm_x4(uint32_t& r0, uint32_t& r1, uint32_t& r2, uint32_t& r3, uint32_t saddr) {
    asm volatile("ldmatrix.sync.aligned.m8n8.x4.shared.b16 {%0,%1,%2,%3}, [%4];"
                 : "=r"(r0), "=r"(r1), "=r"(r2), "=r"(r3) : "r"(saddr));
}

// ---------------- W-prep: dcn weights -> fp16 swizzled [k][o][c'] ----------------
__global__ void wth_prep_kernel(const float* __restrict__ dcn_w) {
    int i = blockIdx.x * blockDim.x + threadIdx.x;
    if (i >= 9*64*64) return;
    int k = i >> 12;
    int rest = i & 4095;
    int o = rest >> 6;
    int c = rest & 63;
    int u = c >> 3;
    int pos = (((u ^ (o & 7)) << 3) | (c & 7));
    g_wth[k*4096 + o*64 + pos] = __float2half(dcn_w[(o*64 + c)*9 + k]);
}

// ---------------- W-prep: half-conv weights fp16 [icg][tap][oc32][c-swizzled] ----------------
__global__ void hwh_prep_kernel(const float* __restrict__ offm_w) {
    int i = blockIdx.x * blockDim.x + threadIdx.x;
    if (i >= 2*9*32*64) return;
    int c = i & 63;
    int r = i >> 6;
    int oc = r & 31; r >>= 5;
    int tap = r % 9;
    int icg = r / 9;
    float v = 0.f;
    if (oc < 27) v = offm_w[(oc*128 + icg*64 + c)*9 + tap];
    int u = c >> 3;
    int pos = (((u ^ (oc & 7)) << 3) | (c & 7));
    g_hwh[(((size_t)icg*9 + tap)*32 + oc)*64 + pos] = __float2half(v);
}

// ---------------- kernel A: 3->64 conv3x3 + bias + PReLU -> NHWC fp16 directly ----------------
__global__ void __launch_bounds__(256) init_conv_kernel(
    const float* __restrict__ x, const float* __restrict__ wgt,
    const float* __restrict__ bias, const float* __restrict__ prelu_a)
{
    __shared__ float sx[3][18][18];
    __shared__ __align__(8) float sw[27*64];
    __shared__ __align__(8) float sb[64];
    int tid = threadIdx.x;
    int n = blockIdx.y;
    int ty0 = (blockIdx.x >> 3) * 16;
    int tx0 = (blockIdx.x & 7) * 16;

    for (int idx = tid; idx < 1728; idx += 256) {
        int oc = idx & 63;
        int r = idx >> 6;
        int ic = r / 9, tap = r % 9;
        sw[idx] = wgt[(oc*3 + ic)*9 + tap];
    }
    if (tid < 64) sb[tid] = bias[tid];

    const float* xin = x + n*3*HW;
    for (int idx = tid; idx < 3*18*18; idx += 256) {
        int c = idx / 324;
        int r = (idx / 18) % 18;
        int col = idx % 18;
        int gy = ty0 + r - 1, gx = tx0 + col - 1;
        float v = 0.f;
        if (gy >= 0 && gy < H && gx >= 0 && gx < W) v = xin[c*HW + gy*W + gx];
        sx[c][r][col] = v;
    }
    __syncthreads();

    int ly = tid >> 4, lx = tid & 15;
    ull acc2[32];
    #pragma unroll
    for (int o2 = 0; o2 < 32; o2++) acc2[o2] = *(const ull*)&sb[2*o2];

    for (int ic = 0; ic < 3; ic++) {
        #pragma unroll
        for (int tap = 0; tap < 9; tap++) {
            int dy = tap / 3, dx = tap % 3;
            float v = sx[ic][ly + dy][lx + dx];
            ull v2 = pk2(v, v);
            const ull* wp = (const ull*)&sw[(ic*9 + tap)*64];
            #pragma unroll
            for (int o2 = 0; o2 < 32; o2++) ffma2(acc2[o2], v2, wp[o2]);
        }
    }
    float a = prelu_a[0];
    int pix = (ty0 + ly)*W + (tx0 + lx);
    __half* nd = g_fnhwc_h + ((size_t)n*HW + pix)*64;
    #pragma unroll
    for (int g4 = 0; g4 < 8; g4++) {
        uint4 pkv;
        uint32_t* pp = (uint32_t*)&pkv;
        #pragma unroll
        for (int i = 0; i < 4; i++) {
            float2 f = upk2(acc2[g4*4 + i]);
            float h0v = (f.x > 0.f) ? f.x : a*f.x;
            float h1v = (f.y > 0.f) ? f.y : a*f.y;
            __half2 h = __float22half2_rn(make_float2(h0v, h1v));
            pp[i] = *(uint32_t*)&h;
        }
        *(uint4*)(nd + g4*8) = pkv;
    }
}

// ---------------- kernel B v9: half offset-conv via HMMA + ldmatrix ----------------
// 128 threads (4 warps); block = one row y, 128 px, one task (b,s).
// smem: input tile 3 planes x 132 rows x 128B (50688) + 2x 4KB weight buffers.
__global__ void __launch_bounds__(128, 3) half_conv_kernel()
{
    extern __shared__ __align__(16) char Sb[];
    const int WOFF = 50688;
    int tid = threadIdx.x;
    int task = blockIdx.y;
    int b = task / 6, s = task % 6;
    int tsel = (s == 0) ? 0 : (s - 1);
    int icg  = (s == 0) ? 0 : 1;
    int y = blockIdx.x;

    const __half* fbh = g_fnhwc_h + (size_t)(b*TT + tsel)*HW*64;
    const char* wbase = (const char*)(g_hwh + (size_t)icg*9*32*64);
    uint32_t sbs = (uint32_t)__cvta_generic_to_shared(Sb);

    // zero halo columns t=0 and t=129
    if (tid < 48) {
        int r = tid / 16;
        int side = (tid >> 3) & 1;
        int qq = tid & 7;
        int t = side ? 129 : 0;
        uint4 z = make_uint4(0, 0, 0, 0);
        *(uint4*)(Sb + (r*132 + t)*128 + ((qq ^ (t & 7)) << 4)) = z;
    }
    // interior: 3 planes x 128 t x 8 ch8-units
    #pragma unroll
    for (int i = 0; i < 24; i++) {
        int idx = tid + i*128;
        int r = idx >> 10;
        int rem = idx & 1023;
        int t = 1 + (rem >> 3);
        int qq = rem & 7;
        int gy = y + r - 1;
        uint4 v = make_uint4(0, 0, 0, 0);
        if (gy >= 0 && gy < H) v = *(const uint4*)(fbh + ((size_t)gy*W + (t - 1))*64 + qq*8);
        *(uint4*)(Sb + (r*132 + t)*128 + ((qq ^ (t & 7)) << 4)) = v;
    }

    // prologue: stage tap 0 weights (4KB linear, swizzle prebaked)
    {
        #pragma unroll
        for (int i2 = 0; i2 < 2; i2++) {
            int idx = tid + i2*128;
            cp_async16(sbs + WOFF + idx*16, wbase + idx*16, true);
        }
        asm volatile("cp.async.commit_group;");
    }

    int lane = tid & 31;
    int warp = tid >> 5;
    int r4 = lane >> 2;
    int c2 = lane & 3;
    int w32 = warp * 32;

    // ldmatrix lane invariants
    int lrow  = lane & 7;
    int lhalf = (lane >> 3) & 1;   // +8 rows for A
    int lkhi  = lane >> 4;         // k-hi unit for A
    int aRowOff = (lhalf*8 + lrow)*128;
    int bT0 = w32 + (lane >> 3)*8 + lrow;   // B row (before +dx)

    float acc[2][4][4];
    #pragma unroll
    for (int mt = 0; mt < 2; mt++)
        #pragma unroll
        for (int nt = 0; nt < 4; nt++)
            #pragma unroll
            for (int f = 0; f < 4; f++) acc[mt][nt][f] = 0.f;

    #pragma unroll
    for (int tap = 0; tap < 9; tap++) {
        int buf = tap & 1;
        if (tap < 8) {
            #pragma unroll
            for (int i2 = 0; i2 < 2; i2++) {
                int idx = tid + i2*128;
                cp_async16(sbs + WOFF + (buf^1)*4096 + idx*16, wbase + (tap+1)*4096 + idx*16, true);
            }
            asm volatile("cp.async.commit_group;");
            asm volatile("cp.async.wait_group 1;");
        } else {
            asm volatile("cp.async.wait_group 0;");
        }
        __syncthreads();

        int dy = tap / 3, dx = tap % 3;
        int t = bT0 + dx;
        uint32_t bRow = sbs + (dy*132 + t)*128;
        int tw = t & 7;
        uint32_t wBuf = sbs + WOFF + buf*4096;

        #pragma unroll
        for (int ks = 0; ks < 4; ks++) {
            uint32_t afr[2][4];
            #pragma unroll
            for (int mt = 0; mt < 2; mt++) {
                uint32_t sa = wBuf + mt*16*128 + aRowOff + ((uint32_t)((ks*2 + lkhi) ^ lrow) << 4);
                ldsm_x4(afr[mt][0], afr[mt][1], afr[mt][2], afr[mt][3], sa);
            }
            uint32_t blo[4], bhi[4];
            {
                uint32_t sb0 = bRow + ((uint32_t)((ks*2) ^ tw) << 4);
                ldsm_x4(blo[0], blo[1], blo[2], blo[3], sb0);
                uint32_t sb1 = bRow + ((uint32_t)((ks*2 + 1) ^ tw) << 4);
                ldsm_x4(bhi[0], bhi[1], bhi[2], bhi[3], sb1);
            }
            #pragma unroll
            for (int mt = 0; mt < 2; mt++)
                #pragma unroll
                for (int nt = 0; nt < 4; nt++) {
                    uint32_t bb[2] = { blo[nt], bhi[nt] };
                    mma16816(acc[mt][nt], afr[mt], bb);
                }
        }
        __syncthreads();   // release buf for stage at tap+2
    }

    // output: 27 real oc of 32, fp32
    float* dst = g_half + (size_t)task*27*HW + y*W;
    #pragma unroll
    for (int mt = 0; mt < 2; mt++) {
        int oc0 = mt*16 + r4;
        int oc1 = oc0 + 8;
        #pragma unroll
        for (int nt = 0; nt < 4; nt++) {
            int px = w32 + nt*8 + c2*2;
            if (oc0 < 27) {
                float2 v; v.x = acc[mt][nt][0]; v.y = acc[mt][nt][1];
                *(float2*)(dst + (size_t)oc0*HW + px) = v;
            }
            if (oc1 < 27) {
                float2 v; v.x = acc[mt][nt][2]; v.y = acc[mt][nt][3];
                *(float2*)(dst + (size_t)oc1*HW + px) = v;
            }
        }
    }
}

// ---------------- kernel C v5: dcn HMMA, fp16 feature gather (R15 verbatim) ----------------
__global__ void __launch_bounds__(128, 4) dcn_kernel(
    const float* __restrict__ offm_b, const float* __restrict__ dcn_b,
    float* __restrict__ out)
{
    __shared__ __align__(16) __half S_h[128*64];
    __shared__ __align__(16) __half W_h[64*64];
    __shared__ int   sAi[4][128];
    __shared__ float sWm[4][128];

    int tid = threadIdx.x;
    int jb = blockIdx.y;
    int j = jb >> 1, b = jb & 1;
    int y = blockIdx.x;

    const __half* fbh = g_fnhwc_h + (size_t)(b*TT + j)*HW*64;
    const float* h0 = g_half + (size_t)((b*6 + 0)*27)*HW;
    const float* h1 = g_half + (size_t)((b*6 + 1 + j)*27)*HW;

    int lane = tid & 31;
    int warp = tid >> 5;
    int r4 = lane >> 2;
    int c2 = lane & 3;
    int w32 = warp * 32;

    float acc[4][4][4];
    #pragma unroll
    for (int mt = 0; mt < 4; mt++)
        #pragma unroll
        for (int nt = 0; nt < 4; nt++)
            #pragma unroll
            for (int f = 0; f < 4; f++) acc[mt][nt][f] = 0.f;

    char* Sb = (char*)S_h;
    char* Wb = (char*)W_h;

    for (int k = 0; k < 9; k++) {
        __syncthreads();

        {
            const float4* src4 = (const float4*)(g_wth + k*4096);
            float4* dst4 = (float4*)W_h;
            #pragma unroll
            for (int i = 0; i < 4; i++) dst4[tid + i*128] = src4[tid + i*128];
        }

        {
            int gx = tid;
            int pix = y*W + gx;
            float oy = h0[k*HW + pix] + h1[k*HW + pix] + offm_b[k];
            float ox = h0[(9+k)*HW + pix] + h1[(9+k)*HW + pix] + offm_b[9+k];
            float mm = h0[(18+k)*HW + pix] + h1[(18+k)*HW + pix] + offm_b[18+k];
            float mask = 1.f / (1.f + expf(-mm));
            float py  = (float)(y + (k/3) - 1) + oy;
            float pxf = (float)(gx + (k%3) - 1) + ox;
            float y0f = floorf(py), x0f = floorf(pxf);
            float lyf = py - y0f, lxf = pxf - x0f;
            int yi = (int)y0f, xi = (int)x0f;
            bool vy0 = (yi >= 0) & (yi < H);
            bool vy1 = (yi >= -1) & (yi < H-1);
            bool vx0 = (xi >= 0) & (xi < W);
            bool vx1 = (xi >= -1) & (xi < W-1);
            int yc0 = min(max(yi, 0), H-1);
            int yc1 = min(max(yi+1, 0), H-1);
            int xc0 = min(max(xi, 0), W-1);
            int xc1 = min(max(xi+1, 0), W-1);
            float wy0 = 1.f - lyf, wy1 = lyf, wx0 = 1.f - lxf, wx1 = lxf;
            sAi[0][tid] = (yc0*W + xc0) * 64;  sWm[0][tid] = (vy0 && vx0) ? wy0*wx0*mask : 0.f;
            sAi[1][tid] = (yc0*W + xc1) * 64;  sWm[1][tid] = (vy0 && vx1) ? wy0*wx1*mask : 0.f;
            sAi[2][tid] = (yc1*W + xc0) * 64;  sWm[2][tid] = (vy1 && vx0) ? wy1*wx0*mask : 0.f;
            sAi[3][tid] = (yc1*W + xc1) * 64;  sWm[3][tid] = (vy1 && vx1) ? wy1*wx1*mask : 0.f;
        }
        __syncthreads();

        #pragma unroll
        for (int it = 0; it < 8; it++) {
            int task = tid + it*128;
            int px = task >> 3;
            int qq = task & 7;
            int a0 = sAi[0][px], a1 = sAi[1][px];
            int a2 = sAi[2][px], a3 = sAi[3][px];
            ull w0 = pk2(sWm[0][px], sWm[0][px]);
            ull w1 = pk2(sWm[1][px], sWm[1][px]);
            ull w2 = pk2(sWm[2][px], sWm[2][px]);
            ull w3 = pk2(sWm[3][px], sWm[3][px]);
            uint4 v0 = *(const uint4*)(fbh + a0 + qq*8);
            uint4 v1 = *(const uint4*)(fbh + a1 + qq*8);
            uint4 v2 = *(const uint4*)(fbh + a2 + qq*8);
            uint4 v3 = *(const uint4*)(fbh + a3 + qq*8);
            const uint32_t* p0 = (const uint32_t*)&v0;
            const uint32_t* p1 = (const uint32_t*)&v1;
            const uint32_t* p2 = (const uint32_t*)&v2;
            const uint32_t* p3 = (const uint32_t*)&v3;
            uint4 outv;
            uint32_t* po = (uint32_t*)&outv;
            #pragma unroll
            for (int i = 0; i < 4; i++) {
                float2 f0 = __half22float2(*(const __half2*)&p0[i]);
                float2 f1 = __half22float2(*(const __half2*)&p1[i]);
                float2 f2 = __half22float2(*(const __half2*)&p2[i]);
                float2 f3 = __half22float2(*(const __half2*)&p3[i]);
                ull r = 0ULL;
                ffma2(r, w0, pk2(f0.x, f0.y));
                ffma2(r, w1, pk2(f1.x, f1.y));
                ffma2(r, w2, pk2(f2.x, f2.y));
                ffma2(r, w3, pk2(f3.x, f3.y));
                float2 rf = upk2(r);
                __half2 h = __float22half2_rn(rf);
                po[i] = *(uint32_t*)&h;
            }
            int byteoff = px*128 + ((qq ^ (px & 7)) << 4);
            *(uint4*)(Sb + byteoff) = outv;
        }
        __syncthreads();

        #pragma unroll
        for (int ks = 0; ks < 4; ks++) {
            int u0 = (ks*2) ^ r4;
            int u1 = (ks*2 + 1) ^ r4;
            int bo0 = (u0 << 4) | (c2 << 2);
            int bo1 = (u1 << 4) | (c2 << 2);

            uint32_t afr[4][4];
            #pragma unroll
            for (int mt = 0; mt < 4; mt++) {
                char* wr = Wb + (mt*16 + r4)*128;
                afr[mt][0] = *(uint32_t*)(wr + bo0);
                afr[mt][1] = *(uint32_t*)(wr + 8*128 + bo0);
                afr[mt][2] = *(uint32_t*)(wr + bo1);
                afr[mt][3] = *(uint32_t*)(wr + 8*128 + bo1);
            }
            uint32_t bfr[4][2];
            #pragma unroll
            for (int nt = 0; nt < 4; nt++) {
                char* sr = Sb + (w32 + nt*8 + r4)*128;
                bfr[nt][0] = *(uint32_t*)(sr + bo0);
                bfr[nt][1] = *(uint32_t*)(sr + bo1);
            }
            #pragma unroll
            for (int mt = 0; mt < 4; mt++)
                #pragma unroll
                for (int nt = 0; nt < 4; nt++)
                    mma16816(acc[mt][nt], afr[mt], bfr[nt]);
        }
    }

    #pragma unroll
    for (int mt = 0; mt < 4; mt++) {
        int oc = mt*16 + r4;
        float bi0 = __ldg(&dcn_b[oc]);
        float bi8 = __ldg(&dcn_b[oc + 8]);
        #pragma unroll
        for (int nt = 0; nt < 4; nt++) {
            int px = w32 + nt*8 + c2*2;
            float* o0 = out + ((size_t)jb*64 + oc)*HW + y*W + px;
            float* o8 = out + ((size_t)jb*64 + oc + 8)*HW + y*W + px;
            float2 v0, v1;
            v0.x = acc[mt][nt][0] + bi0; v0.y = acc[mt][nt][1] + bi0;
            v1.x = acc[mt][nt][2] + bi8; v1.y = acc[mt][nt][3] + bi8;
            *(float2*)o0 = v0;
            *(float2*)o8 = v1;
        }
    }
}

// ---------------- launch ----------------
extern "C" void kernel_launch(void* const* d_in, const int* in_sizes, int n_in,
                              void* d_out, int out_size) {
    const float* x       = (const float*)d_in[0];
    const float* init_w  = (const float*)d_in[1];
    const float* init_b  = (const float*)d_in[2];
    const float* prelu_a = (const float*)d_in[3];
    const float* offm_w  = (const float*)d_in[4];
    const float* offm_b  = (const float*)d_in[5];
    const float* dcn_w   = (const float*)d_in[6];
    const float* dcn_b   = (const float*)d_in[7];
    float* out = (float*)d_out;

    static bool attr_set = false;
    if (!attr_set) {
        cudaFuncSetAttribute(half_conv_kernel, cudaFuncAttributeMaxDynamicSharedMemorySize, 58880);
        attr_set = true;
    }

    wth_prep_kernel<<<(9*64*64 + 255)/256, 256>>>(dcn_w);
    hwh_prep_kernel<<<(2*9*32*64 + 255)/256, 256>>>(offm_w);
    init_conv_kernel<<<dim3(64, 10), 256>>>(x, init_w, init_b, prelu_a);
    half_conv_kernel<<<dim3(128, 12), 128, 58880>>>();
    dcn_kernel<<<dim3(128, 10), 128>>>(offm_b, dcn_b, out);
}